// round 10
// baseline (speedup 1.0000x reference)
#include <cuda_runtime.h>
#include <cuda_bf16.h>
#include <cuda_fp16.h>
#include <cstddef>
#include <cstdint>

// Problem constants
#define B_SZ   2
#define NSEQ   2048
#define DMODEL 1024
#define NHEAD  16
#define HDIM   64
#define MTOT   (B_SZ * NSEQ)      // 4096
#define BH     (B_SZ * NHEAD)     // 32

// ---------------------------------------------------------------------------
// Scratch (static device arrays; no allocation allowed)
// x / W / A in fp16 hi + scaled-lo splits (GEMM path);  Q/K/V in bf16 splits
// (flash path, unchanged).
// ---------------------------------------------------------------------------
__device__ __half g_xhi[MTOT * DMODEL];
__device__ __half g_xlo[MTOT * DMODEL];
__device__ __half g_W0hi[DMODEL * DMODEL];
__device__ __half g_W0lo[DMODEL * DMODEL];
__device__ __half g_W1hi[DMODEL * DMODEL];
__device__ __half g_W1lo[DMODEL * DMODEL];
__device__ __half g_W2hi[DMODEL * DMODEL];
__device__ __half g_W2lo[DMODEL * DMODEL];
__device__ __half g_W3hi[DMODEL * DMODEL];
__device__ __half g_W3lo[DMODEL * DMODEL];
__device__ __half g_Ahi[MTOT * DMODEL];
__device__ __half g_Alo[MTOT * DMODEL];
__device__ __nv_bfloat16 g_Qhi[BH * NSEQ * HDIM];
__device__ __nv_bfloat16 g_Qlo[BH * NSEQ * HDIM];
__device__ __nv_bfloat16 g_Khi[BH * NSEQ * HDIM];
__device__ __nv_bfloat16 g_Klo[BH * NSEQ * HDIM];
__device__ __nv_bfloat16 g_Vhi[BH * NSEQ * HDIM];
__device__ __nv_bfloat16 g_Vlo[BH * NSEQ * HDIM];

#define LOSCALE 4096.0f
#define INV_LOSCALE (1.0f / 4096.0f)

// ---------------------------------------------------------------------------
// PTX helpers
// ---------------------------------------------------------------------------
__device__ __forceinline__ uint32_t s2u(const void* p) {
    uint32_t r;
    asm("{ .reg .u64 t; cvta.to.shared.u64 t, %1; cvt.u32.u64 %0, t; }" : "=r"(r) : "l"(p));
    return r;
}
__device__ __forceinline__ void cpa16(uint32_t dst, const void* src) {
    asm volatile("cp.async.cg.shared.global [%0], [%1], 16;" :: "r"(dst), "l"(src));
}
__device__ __forceinline__ void ldsm_x4(uint32_t* r, uint32_t addr) {
    asm volatile("ldmatrix.sync.aligned.m8n8.x4.shared.b16 {%0,%1,%2,%3}, [%4];"
                 : "=r"(r[0]), "=r"(r[1]), "=r"(r[2]), "=r"(r[3]) : "r"(addr));
}
__device__ __forceinline__ void ldsm_x4_t(uint32_t* r, uint32_t addr) {
    asm volatile("ldmatrix.sync.aligned.m8n8.x4.trans.shared.b16 {%0,%1,%2,%3}, [%4];"
                 : "=r"(r[0]), "=r"(r[1]), "=r"(r[2]), "=r"(r[3]) : "r"(addr));
}
// bf16 inputs, f32 acc (flash)
__device__ __forceinline__ void mma16816(float* c, const uint32_t* a, const uint32_t* b) {
    asm volatile("mma.sync.aligned.m16n8k16.row.col.f32.bf16.bf16.f32 "
                 "{%0,%1,%2,%3}, {%4,%5,%6,%7}, {%8,%9}, {%0,%1,%2,%3};"
                 : "+f"(c[0]), "+f"(c[1]), "+f"(c[2]), "+f"(c[3])
                 : "r"(a[0]), "r"(a[1]), "r"(a[2]), "r"(a[3]), "r"(b[0]), "r"(b[1]));
}
// fp16 inputs, f32 acc (GEMM main term)
__device__ __forceinline__ void mma_hf(float* c, const uint32_t* a, const uint32_t* b) {
    asm volatile("mma.sync.aligned.m16n8k16.row.col.f32.f16.f16.f32 "
                 "{%0,%1,%2,%3}, {%4,%5,%6,%7}, {%8,%9}, {%0,%1,%2,%3};"
                 : "+f"(c[0]), "+f"(c[1]), "+f"(c[2]), "+f"(c[3])
                 : "r"(a[0]), "r"(a[1]), "r"(a[2]), "r"(a[3]), "r"(b[0]), "r"(b[1]));
}
// fp16 inputs, fp16 acc (GEMM correction terms — the 2x-rate gamble)
__device__ __forceinline__ void mma_hh(uint32_t* c, const uint32_t* a, const uint32_t* b) {
    asm volatile("mma.sync.aligned.m16n8k16.row.col.f16.f16.f16.f16 "
                 "{%0,%1}, {%2,%3,%4,%5}, {%6,%7}, {%0,%1};"
                 : "+r"(c[0]), "+r"(c[1])
                 : "r"(a[0]), "r"(a[1]), "r"(a[2]), "r"(a[3]), "r"(b[0]), "r"(b[1]));
}
__device__ __forceinline__ float ex2(float x) {
    float y;
    asm("ex2.approx.f32 %0, %1;" : "=f"(y) : "f"(x));
    return y;
}
// bf16 split (flash Q/K/V path)
__device__ __forceinline__ uint32_t pack2_split(float x, float y, uint32_t& lopack) {
    __nv_bfloat16 hx = __float2bfloat16(x);
    __nv_bfloat16 hy = __float2bfloat16(y);
    __nv_bfloat16 lx = __float2bfloat16(x - __bfloat162float(hx));
    __nv_bfloat16 ly = __float2bfloat16(y - __bfloat162float(hy));
    lopack = (uint32_t)__bfloat16_as_ushort(lx) | ((uint32_t)__bfloat16_as_ushort(ly) << 16);
    return (uint32_t)__bfloat16_as_ushort(hx) | ((uint32_t)__bfloat16_as_ushort(hy) << 16);
}
// fp16 split with scaled lo (GEMM path)
__device__ __forceinline__ uint32_t pack2_split_h(float x, float y, uint32_t& lopack) {
    __half hx = __float2half_rn(x);
    __half hy = __float2half_rn(y);
    __half lx = __float2half_rn((x - __half2float(hx)) * LOSCALE);
    __half ly = __float2half_rn((y - __half2float(hy)) * LOSCALE);
    lopack = (uint32_t)__half_as_ushort(lx) | ((uint32_t)__half_as_ushort(ly) << 16);
    return (uint32_t)__half_as_ushort(hx) | ((uint32_t)__half_as_ushort(hy) << 16);
}

// ---------------------------------------------------------------------------
// fp32 -> fp16 hi/scaled-lo splits
// ---------------------------------------------------------------------------
__global__ void split_f16(const float* __restrict__ in,
                          __half* __restrict__ hi, __half* __restrict__ lo, int n4)
{
    int i = blockIdx.x * blockDim.x + threadIdx.x;
    if (i >= n4) return;
    float4 v = reinterpret_cast<const float4*>(in)[i];
    uint2 h, l;
    h.x = pack2_split_h(v.x, v.y, l.x);
    h.y = pack2_split_h(v.z, v.w, l.y);
    reinterpret_cast<uint2*>(hi)[i] = h;
    reinterpret_cast<uint2*>(lo)[i] = l;
}

__global__ void split_f16_w(const float* __restrict__ w0, const float* __restrict__ w1,
                            const float* __restrict__ w2, const float* __restrict__ w3,
                            __half* __restrict__ h0, __half* __restrict__ l0,
                            __half* __restrict__ h1, __half* __restrict__ l1,
                            __half* __restrict__ h2, __half* __restrict__ l2,
                            __half* __restrict__ h3, __half* __restrict__ l3,
                            int n4)
{
    int i = blockIdx.x * blockDim.x + threadIdx.x;
    if (i >= n4) return;
    const float* in; __half *hi, *lo;
    switch (blockIdx.y) {
        case 0: in = w0; hi = h0; lo = l0; break;
        case 1: in = w1; hi = h1; lo = l1; break;
        case 2: in = w2; hi = h2; lo = l2; break;
        default: in = w3; hi = h3; lo = l3; break;
    }
    float4 v = reinterpret_cast<const float4*>(in)[i];
    uint2 h, l;
    h.x = pack2_split_h(v.x, v.y, l.x);
    h.y = pack2_split_h(v.z, v.w, l.y);
    reinterpret_cast<uint2*>(hi)[i] = h;
    reinterpret_cast<uint2*>(lo)[i] = l;
}

// ---------------------------------------------------------------------------
// fp16-split GEMM core: main term f32-acc, corrections into shared fp16-acc.
// 3-stage cp.async pipeline.
// ---------------------------------------------------------------------------
#define TM 128
#define TN 128
#define KC 32
#define CHUNKS (DMODEL / KC)       // 32
#define TILE_B  8192
#define STAGE_B (4 * TILE_B)       // 32 KB
#define GSTAGES 3
#define GEMM_DSMEM (GSTAGES * STAGE_B)   // 96 KB

__device__ __forceinline__ uint32_t swz(uint32_t row, uint32_t chunk) {
    return row * 64u + ((chunk ^ ((row >> 1) & 3u)) << 4);
}

template <int MODE>
__device__ __forceinline__ void gemm_core(
        const __half* __restrict__ Ahi, const __half* __restrict__ Alo,
        const __half* __restrict__ Bhi, const __half* __restrict__ Blo,
        const float* __restrict__ bias, float* __restrict__ C,
        __nv_bfloat16* __restrict__ Chi, __nv_bfloat16* __restrict__ Clo,
        float scale, char* dsm, int m0, int n0)
{
    const uint32_t sbase = s2u(dsm);
    const int tid  = threadIdx.x;
    const int wid  = tid >> 5;
    const int lane = tid & 31;
    const int wm = (wid & 3) * 32;
    const int wn = (wid >> 2) * 64;

    float acc[2][8][4];        // main f32 accumulators
    uint32_t cacc[2][8][2];    // shared fp16 correction accumulators (x LOSCALE)
#pragma unroll
    for (int i = 0; i < 2; i++)
#pragma unroll
        for (int j = 0; j < 8; j++) {
#pragma unroll
            for (int q = 0; q < 4; q++) acc[i][j][q] = 0.f;
            cacc[i][j][0] = 0u; cacc[i][j][1] = 0u;
        }

    const uint32_t lrow = (uint32_t)(tid >> 1);
    const uint32_t lch  = (uint32_t)(tid & 1) * 2;

    auto load_chunk = [&](int ch, int s) {
        const uint32_t sb = sbase + (uint32_t)s * STAGE_B;
        const size_t gA = (size_t)(m0 + lrow) * DMODEL + (size_t)ch * KC + lch * 8;
        const size_t gB = (size_t)(n0 + lrow) * DMODEL + (size_t)ch * KC + lch * 8;
#pragma unroll
        for (int c = 0; c < 2; c++) {
            uint32_t so = swz(lrow, lch + c);
            cpa16(sb + 0 * TILE_B + so, Ahi + gA + c * 8);
            cpa16(sb + 1 * TILE_B + so, Alo + gA + c * 8);
            cpa16(sb + 2 * TILE_B + so, Bhi + gB + c * 8);
            cpa16(sb + 3 * TILE_B + so, Blo + gB + c * 8);
        }
        asm volatile("cp.async.commit_group;" ::: "memory");
    };

    load_chunk(0, 0);
    load_chunk(1, 1);

    int stage = 0;
    for (int ch = 0; ch < CHUNKS; ++ch) {
        if (ch + 1 < CHUNKS) { asm volatile("cp.async.wait_group 1;" ::: "memory"); }
        else                 { asm volatile("cp.async.wait_group 0;" ::: "memory"); }
        __syncthreads();
        if (ch + 2 < CHUNKS) {
            int ps = stage + 2; if (ps >= GSTAGES) ps -= GSTAGES;
            load_chunk(ch + 2, ps);
        }

        const uint32_t sb = sbase + (uint32_t)stage * STAGE_B;
#pragma unroll
        for (int kstep = 0; kstep < 2; kstep++) {
            const uint32_t kc = (uint32_t)kstep * 2;
            uint32_t a_hi[2][4], a_lo[2][4];
#pragma unroll
            for (int mf = 0; mf < 2; mf++) {
                uint32_t row = (uint32_t)(wm + mf * 16 + (lane & 15));
                uint32_t chn = kc + (uint32_t)(lane >> 4);
                ldsm_x4(a_hi[mf], sb + 0 * TILE_B + swz(row, chn));
                ldsm_x4(a_lo[mf], sb + 1 * TILE_B + swz(row, chn));
            }
#pragma unroll
            for (int nf2 = 0; nf2 < 4; nf2++) {
                uint32_t row = (uint32_t)(wn + nf2 * 16 + 8 * (lane >> 4) + (lane & 7));
                uint32_t chn = kc + (uint32_t)((lane >> 3) & 1);
                uint32_t th[4], tl[4];
                ldsm_x4(th, sb + 2 * TILE_B + swz(row, chn));
                ldsm_x4(tl, sb + 3 * TILE_B + swz(row, chn));
                // main term (f32 acc), reuse distance 4
                mma_hf(acc[0][2 * nf2],     a_hi[0], th);
                mma_hf(acc[0][2 * nf2 + 1], a_hi[0], th + 2);
                mma_hf(acc[1][2 * nf2],     a_hi[1], th);
                mma_hf(acc[1][2 * nf2 + 1], a_hi[1], th + 2);
                // correction xh*wl_s (fp16 acc)
                mma_hh(cacc[0][2 * nf2],     a_hi[0], tl);
                mma_hh(cacc[0][2 * nf2 + 1], a_hi[0], tl + 2);
                mma_hh(cacc[1][2 * nf2],     a_hi[1], tl);
                mma_hh(cacc[1][2 * nf2 + 1], a_hi[1], tl + 2);
                // correction xl_s*wh (same fp16 accs, distance 4)
                mma_hh(cacc[0][2 * nf2],     a_lo[0], th);
                mma_hh(cacc[0][2 * nf2 + 1], a_lo[0], th + 2);
                mma_hh(cacc[1][2 * nf2],     a_lo[1], th);
                mma_hh(cacc[1][2 * nf2 + 1], a_lo[1], th + 2);
            }
        }
        if (++stage >= GSTAGES) stage = 0;
    }
    __syncthreads();

#pragma unroll
    for (int mf = 0; mf < 2; mf++) {
        const int rbase = m0 + wm + mf * 16 + (lane >> 2);
#pragma unroll
        for (int nf = 0; nf < 8; nf++) {
            const int n = n0 + wn + nf * 8 + (lane & 3) * 2;
            const float b0 = bias[n], b1 = bias[n + 1];
#pragma unroll
            for (int half = 0; half < 2; half++) {
                const int m = rbase + half * 8;
                float2 cf = __half22float2(
                    *reinterpret_cast<__half2*>(&cacc[mf][nf][half]));
                float v0 = (acc[mf][nf][2 * half]     + cf.x * INV_LOSCALE + b0) * scale;
                float v1 = (acc[mf][nf][2 * half + 1] + cf.y * INV_LOSCALE + b1) * scale;
                if (MODE == 0) {
                    *reinterpret_cast<float2*>(C + (size_t)m * DMODEL + n) =
                        make_float2(v0, v1);
                } else {
                    int h = n >> 6, hd = n & 63;
                    int b  = m >> 11, ns = m & 2047;
                    size_t idx = (((size_t)(b * NHEAD + h) * NSEQ) + ns) * HDIM + hd;
                    uint32_t lp, hp = pack2_split(v0, v1, lp);
                    *reinterpret_cast<uint32_t*>(Chi + idx) = hp;
                    *reinterpret_cast<uint32_t*>(Clo + idx) = lp;
                }
            }
        }
    }
}

// Q pre-scale folds 1/sqrt(HDIM) AND log2(e)
#define QSCALE 0.18033688011112042f

__global__ void __launch_bounds__(256, 2)
gemm_qkv(const __half* __restrict__ xhi, const __half* __restrict__ xlo,
         const __half* __restrict__ w0h, const __half* __restrict__ w0l,
         const __half* __restrict__ w1h, const __half* __restrict__ w1l,
         const __half* __restrict__ w2h, const __half* __restrict__ w2l,
         const float* __restrict__ bq, const float* __restrict__ bk,
         const float* __restrict__ bv,
         __nv_bfloat16* __restrict__ qh, __nv_bfloat16* __restrict__ ql,
         __nv_bfloat16* __restrict__ kh, __nv_bfloat16* __restrict__ kl,
         __nv_bfloat16* __restrict__ vh, __nv_bfloat16* __restrict__ vl)
{
    extern __shared__ char dsm[];
    const int m0 = blockIdx.y * TM;
    const int n0 = blockIdx.x * TN;
    const __half *Bh, *Bl; const float* bias;
    __nv_bfloat16 *Ch, *Cl; float scale;
    switch (blockIdx.z) {
        case 0:  Bh = w0h; Bl = w0l; bias = bq; Ch = qh; Cl = ql; scale = QSCALE; break;
        case 1:  Bh = w1h; Bl = w1l; bias = bk; Ch = kh; Cl = kl; scale = 1.0f;   break;
        default: Bh = w2h; Bl = w2l; bias = bv; Ch = vh; Cl = vl; scale = 1.0f;   break;
    }
    gemm_core<1>(xhi, xlo, Bh, Bl, bias, nullptr, Ch, Cl, scale, dsm, m0, n0);
}

__global__ void __launch_bounds__(256, 2)
gemm_out(const __half* __restrict__ Ahi, const __half* __restrict__ Alo,
         const __half* __restrict__ Bhi, const __half* __restrict__ Blo,
         const float* __restrict__ bias, float* __restrict__ C)
{
    extern __shared__ char dsm[];
    gemm_core<0>(Ahi, Alo, Bhi, Blo, bias, C, nullptr, nullptr, 1.0f, dsm,
                 blockIdx.y * TM, blockIdx.x * TN);
}

// ---------------------------------------------------------------------------
// HMMA flash attention (R7 version, unchanged except fp16 output packing).
// ---------------------------------------------------------------------------
#define FBR 128
#define FBC 64
#define FKT (NSEQ / FBC)          // 32
#define FQHI 0
#define FQLO 16384
#define FSTG0 32768
#define FSTG_B 32768
#define FLASH_DSMEM (32768 + 2 * FSTG_B)   // 96 KB

__device__ __forceinline__ uint32_t swz8(uint32_t row, uint32_t chunk) {
    return row * 128u + ((chunk ^ (row & 7u)) << 4);
}

__global__ void __launch_bounds__(256, 2)
flash_mma(const __nv_bfloat16* __restrict__ Qhi, const __nv_bfloat16* __restrict__ Qlo,
          const __nv_bfloat16* __restrict__ Khi, const __nv_bfloat16* __restrict__ Klo,
          const __nv_bfloat16* __restrict__ Vhi, const __nv_bfloat16* __restrict__ Vlo,
          __half* __restrict__ Ohi, __half* __restrict__ Olo)
{
    extern __shared__ char fsm[];
    const uint32_t sbase = s2u(fsm);

    const int tid  = threadIdx.x;
    const int wid  = tid >> 5;
    const int lane = tid & 31;
    const int bh   = blockIdx.y;
    const int q0   = blockIdx.x * FBR;

    const size_t hb = (size_t)bh * NSEQ * HDIM;
    const __nv_bfloat16* Qh = Qhi + hb; const __nv_bfloat16* Ql = Qlo + hb;
    const __nv_bfloat16* Kh = Khi + hb; const __nv_bfloat16* Kl = Klo + hb;
    const __nv_bfloat16* Vh = Vhi + hb; const __nv_bfloat16* Vl = Vlo + hb;

    {
        const uint32_t row = (uint32_t)(tid >> 1);
        const uint32_t c0  = (uint32_t)(tid & 1) * 4;
        const size_t g = (size_t)(q0 + row) * HDIM + c0 * 8;
#pragma unroll
        for (int c = 0; c < 4; c++) {
            uint32_t sw = swz8(row, c0 + c);
            cpa16(sbase + FQHI + sw, Qh + g + c * 8);
            cpa16(sbase + FQLO + sw, Ql + g + c * 8);
        }
    }
    auto load_kv = [&](int kt, int s) {
        const uint32_t sb = sbase + FSTG0 + (uint32_t)s * FSTG_B;
        const uint32_t row = (uint32_t)(tid >> 2);
        const uint32_t cc  = (uint32_t)(tid & 3) * 2;
        const size_t g = (size_t)(kt * FBC + row) * HDIM + cc * 8;
#pragma unroll
        for (int j = 0; j < 2; j++) {
            uint32_t sw = swz8(row, cc + j);
            cpa16(sb +     0u + sw, Kh + g + j * 8);
            cpa16(sb +  8192u + sw, Kl + g + j * 8);
            cpa16(sb + 16384u + sw, Vh + g + j * 8);
            cpa16(sb + 24576u + sw, Vl + g + j * 8);
        }
        asm volatile("cp.async.commit_group;" ::: "memory");
    };
    load_kv(0, 0);

    float o[8][4];
#pragma unroll
    for (int j = 0; j < 8; j++)
#pragma unroll
        for (int q = 0; q < 4; q++) o[j][q] = 0.f;
    float m0s = -1e30f, m1s = -1e30f, l0s = 0.f, l1s = 0.f;

    const uint32_t la15 = (uint32_t)(lane & 15);
    const uint32_t la7  = (uint32_t)(lane & 7);
    const uint32_t lb8  = 8u * (uint32_t)(lane >> 4);
    const uint32_t lbc  = (uint32_t)((lane >> 3) & 1);
    const uint32_t lac  = (uint32_t)(lane >> 4);

    for (int kt = 0; kt < FKT; kt++) {
        asm volatile("cp.async.wait_group 0;" ::: "memory");
        __syncthreads();
        if (kt + 1 < FKT) load_kv(kt + 1, (kt + 1) & 1);

        const uint32_t sb = sbase + FSTG0 + (uint32_t)(kt & 1) * FSTG_B;
        float acc[8][4];
#pragma unroll
        for (int j = 0; j < 8; j++)
#pragma unroll
            for (int q = 0; q < 4; q++) acc[j][q] = 0.f;

#pragma unroll
        for (int kf = 0; kf < 4; kf++) {
            uint32_t aQh[4], aQl[4];
            uint32_t qad = swz8((uint32_t)(wid * 16) + la15, 2u * kf + lac);
            ldsm_x4(aQh, sbase + FQHI + qad);
            ldsm_x4(aQl, sbase + FQLO + qad);
#pragma unroll
            for (int np = 0; np < 4; np++) {
                uint32_t ad = swz8((uint32_t)(np * 16) + la7 + lb8, 2u * kf + lbc);
                uint32_t kh[4], kl[4];
                ldsm_x4(kh, sb + 0u + ad);
                ldsm_x4(kl, sb + 8192u + ad);
                mma16816(acc[2 * np],     aQh, kh);
                mma16816(acc[2 * np + 1], aQh, kh + 2);
                mma16816(acc[2 * np],     aQh, kl);
                mma16816(acc[2 * np + 1], aQh, kl + 2);
                mma16816(acc[2 * np],     aQl, kh);
                mma16816(acc[2 * np + 1], aQl, kh + 2);
            }
        }

        float mx0 = -1e30f, mx1 = -1e30f;
#pragma unroll
        for (int nf = 0; nf < 8; nf++) {
            mx0 = fmaxf(mx0, fmaxf(acc[nf][0], acc[nf][1]));
            mx1 = fmaxf(mx1, fmaxf(acc[nf][2], acc[nf][3]));
        }
        mx0 = fmaxf(mx0, __shfl_xor_sync(0xffffffffu, mx0, 1));
        mx0 = fmaxf(mx0, __shfl_xor_sync(0xffffffffu, mx0, 2));
        mx1 = fmaxf(mx1, __shfl_xor_sync(0xffffffffu, mx1, 1));
        mx1 = fmaxf(mx1, __shfl_xor_sync(0xffffffffu, mx1, 2));
        float mn0 = fmaxf(m0s, mx0), mn1 = fmaxf(m1s, mx1);
        float al0 = ex2(m0s - mn0), al1 = ex2(m1s - mn1);
        m0s = mn0; m1s = mn1;
        float sum0 = 0.f, sum1 = 0.f;
#pragma unroll
        for (int nf = 0; nf < 8; nf++) {
            acc[nf][0] = ex2(acc[nf][0] - mn0);
            acc[nf][1] = ex2(acc[nf][1] - mn0);
            acc[nf][2] = ex2(acc[nf][2] - mn1);
            acc[nf][3] = ex2(acc[nf][3] - mn1);
            sum0 += acc[nf][0] + acc[nf][1];
            sum1 += acc[nf][2] + acc[nf][3];
        }
        sum0 += __shfl_xor_sync(0xffffffffu, sum0, 1);
        sum0 += __shfl_xor_sync(0xffffffffu, sum0, 2);
        sum1 += __shfl_xor_sync(0xffffffffu, sum1, 1);
        sum1 += __shfl_xor_sync(0xffffffffu, sum1, 2);
        l0s = l0s * al0 + sum0;
        l1s = l1s * al1 + sum1;
#pragma unroll
        for (int nf = 0; nf < 8; nf++) {
            o[nf][0] *= al0; o[nf][1] *= al0;
            o[nf][2] *= al1; o[nf][3] *= al1;
        }

#pragma unroll
        for (int kf = 0; kf < 4; kf++) {
            uint32_t pH[4], pL[4];
            pH[0] = pack2_split(acc[2 * kf][0],     acc[2 * kf][1],     pL[0]);
            pH[1] = pack2_split(acc[2 * kf][2],     acc[2 * kf][3],     pL[1]);
            pH[2] = pack2_split(acc[2 * kf + 1][0], acc[2 * kf + 1][1], pL[2]);
            pH[3] = pack2_split(acc[2 * kf + 1][2], acc[2 * kf + 1][3], pL[3]);
#pragma unroll
            for (int dp = 0; dp < 4; dp++) {
                uint32_t ad = swz8((uint32_t)(kf * 16) + la15, 2u * dp + lac);
                uint32_t vh[4], vl[4];
                ldsm_x4_t(vh, sb + 16384u + ad);
                ldsm_x4_t(vl, sb + 24576u + ad);
                mma16816(o[2 * dp],     pH, vh);
                mma16816(o[2 * dp + 1], pH, vh + 2);
                mma16816(o[2 * dp],     pH, vl);
                mma16816(o[2 * dp + 1], pH, vl + 2);
                mma16816(o[2 * dp],     pL, vh);
                mma16816(o[2 * dp + 1], pL, vh + 2);
            }
        }
    }

    // normalize + write fp16 hi / scaled-lo to [B,N,D] (feeds fp16 O-proj)
    const int bb = bh >> 4;
    const int h  = bh & 15;
    const float inv0 = 1.f / l0s, inv1 = 1.f / l1s;
    const int qlo = q0 + wid * 16 + (lane >> 2);
#pragma unroll
    for (int nf = 0; nf < 8; nf++) {
        const int gcol = h * HDIM + nf * 8 + (lane & 3) * 2;
        uint32_t lp, hp;
        hp = pack2_split_h(o[nf][0] * inv0, o[nf][1] * inv0, lp);
        size_t i0 = ((size_t)(bb * NSEQ + qlo)) * DMODEL + gcol;
        *reinterpret_cast<uint32_t*>(Ohi + i0) = hp;
        *reinterpret_cast<uint32_t*>(Olo + i0) = lp;
        hp = pack2_split_h(o[nf][2] * inv1, o[nf][3] * inv1, lp);
        size_t i1 = ((size_t)(bb * NSEQ + qlo + 8)) * DMODEL + gcol;
        *reinterpret_cast<uint32_t*>(Ohi + i1) = hp;
        *reinterpret_cast<uint32_t*>(Olo + i1) = lp;
    }
}

// ---------------------------------------------------------------------------
// Launch
// ---------------------------------------------------------------------------
extern "C" void kernel_launch(void* const* d_in, const int* in_sizes, int n_in,
                              void* d_out, int out_size)
{
    const float* x  = (const float*)d_in[0];
    const float* Wq = (const float*)d_in[1];
    const float* bq = (const float*)d_in[2];
    const float* Wk = (const float*)d_in[3];
    const float* bk = (const float*)d_in[4];
    const float* Wv = (const float*)d_in[5];
    const float* bv = (const float*)d_in[6];
    const float* Wo = (const float*)d_in[7];
    const float* bo = (const float*)d_in[8];
    float* out = (float*)d_out;

    __half *xhi, *xlo, *w0h, *w0l, *w1h, *w1l, *w2h, *w2l, *w3h, *w3l, *ahi, *alo;
    __nv_bfloat16 *qh, *ql, *kh, *kl, *vh, *vl;
    cudaGetSymbolAddress((void**)&xhi, g_xhi);  cudaGetSymbolAddress((void**)&xlo, g_xlo);
    cudaGetSymbolAddress((void**)&w0h, g_W0hi); cudaGetSymbolAddress((void**)&w0l, g_W0lo);
    cudaGetSymbolAddress((void**)&w1h, g_W1hi); cudaGetSymbolAddress((void**)&w1l, g_W1lo);
    cudaGetSymbolAddress((void**)&w2h, g_W2hi); cudaGetSymbolAddress((void**)&w2l, g_W2lo);
    cudaGetSymbolAddress((void**)&w3h, g_W3hi); cudaGetSymbolAddress((void**)&w3l, g_W3lo);
    cudaGetSymbolAddress((void**)&ahi, g_Ahi);  cudaGetSymbolAddress((void**)&alo, g_Alo);
    cudaGetSymbolAddress((void**)&qh, g_Qhi);   cudaGetSymbolAddress((void**)&ql, g_Qlo);
    cudaGetSymbolAddress((void**)&kh, g_Khi);   cudaGetSymbolAddress((void**)&kl, g_Klo);
    cudaGetSymbolAddress((void**)&vh, g_Vhi);   cudaGetSymbolAddress((void**)&vl, g_Vlo);

    cudaFuncSetAttribute(gemm_qkv, cudaFuncAttributeMaxDynamicSharedMemorySize, GEMM_DSMEM);
    cudaFuncSetAttribute(gemm_out, cudaFuncAttributeMaxDynamicSharedMemorySize, GEMM_DSMEM);
    cudaFuncSetAttribute(flash_mma, cudaFuncAttributeMaxDynamicSharedMemorySize, FLASH_DSMEM);

    split_f16<<<MTOT * DMODEL / 4 / 256, 256>>>(x, xhi, xlo, MTOT * DMODEL / 4);
    dim3 wgrid(DMODEL * DMODEL / 4 / 256, 4);
    split_f16_w<<<wgrid, 256>>>(Wq, Wk, Wv, Wo,
                                w0h, w0l, w1h, w1l, w2h, w2l, w3h, w3l,
                                DMODEL * DMODEL / 4);

    dim3 qgrid(DMODEL / TN, MTOT / TM, 3);   // (8, 32, 3)
    gemm_qkv<<<qgrid, 256, GEMM_DSMEM>>>(xhi, xlo, w0h, w0l, w1h, w1l, w2h, w2l,
                                         bq, bk, bv, qh, ql, kh, kl, vh, vl);

    dim3 agrid(NSEQ / FBR, BH);              // (16, 32)
    flash_mma<<<agrid, 256, FLASH_DSMEM>>>(qh, ql, kh, kl, vh, vl, ahi, alo);

    dim3 ogrid(DMODEL / TN, MTOT / TM);      // (8, 32)
    gemm_out<<<ogrid, 256, GEMM_DSMEM>>>(ahi, alo, w3h, w3l, bo, out);
}

// round 13
// speedup vs baseline: 1.4159x; 1.4159x over previous
#include <cuda_runtime.h>
#include <cuda_bf16.h>
#include <cuda_fp16.h>
#include <cstddef>
#include <cstdint>

// Problem constants
#define B_SZ   2
#define NSEQ   2048
#define DMODEL 1024
#define NHEAD  16
#define HDIM   64
#define MTOT   (B_SZ * NSEQ)      // 4096
#define BH     (B_SZ * NHEAD)     // 32

// ---------------------------------------------------------------------------
// Scratch (static device arrays; no allocation allowed)
// ---------------------------------------------------------------------------
__device__ __nv_bfloat16 g_xhi[MTOT * DMODEL];
__device__ __nv_bfloat16 g_xlo[MTOT * DMODEL];
__device__ __nv_bfloat16 g_W0hi[DMODEL * DMODEL];
__device__ __nv_bfloat16 g_W0lo[DMODEL * DMODEL];
__device__ __nv_bfloat16 g_W1hi[DMODEL * DMODEL];
__device__ __nv_bfloat16 g_W1lo[DMODEL * DMODEL];
__device__ __nv_bfloat16 g_W2hi[DMODEL * DMODEL];
__device__ __nv_bfloat16 g_W2lo[DMODEL * DMODEL];
__device__ __nv_bfloat16 g_W3hi[DMODEL * DMODEL];
__device__ __nv_bfloat16 g_W3lo[DMODEL * DMODEL];
__device__ __nv_bfloat16 g_Ahi[MTOT * DMODEL];
__device__ __nv_bfloat16 g_Alo[MTOT * DMODEL];
// QKV single fp16 (2^-12 mantissa: measured-scaled flash error ~3.4e-4)
__device__ __half g_Q[BH * NSEQ * HDIM];
__device__ __half g_K[BH * NSEQ * HDIM];
__device__ __half g_V[BH * NSEQ * HDIM];

// ---------------------------------------------------------------------------
// PTX helpers
// ---------------------------------------------------------------------------
__device__ __forceinline__ uint32_t s2u(const void* p) {
    uint32_t r;
    asm("{ .reg .u64 t; cvta.to.shared.u64 t, %1; cvt.u32.u64 %0, t; }" : "=r"(r) : "l"(p));
    return r;
}
__device__ __forceinline__ void cpa16(uint32_t dst, const void* src) {
    asm volatile("cp.async.cg.shared.global [%0], [%1], 16;" :: "r"(dst), "l"(src));
}
__device__ __forceinline__ void ldsm_x4(uint32_t* r, uint32_t addr) {
    asm volatile("ldmatrix.sync.aligned.m8n8.x4.shared.b16 {%0,%1,%2,%3}, [%4];"
                 : "=r"(r[0]), "=r"(r[1]), "=r"(r[2]), "=r"(r[3]) : "r"(addr));
}
__device__ __forceinline__ void ldsm_x4_t(uint32_t* r, uint32_t addr) {
    asm volatile("ldmatrix.sync.aligned.m8n8.x4.trans.shared.b16 {%0,%1,%2,%3}, [%4];"
                 : "=r"(r[0]), "=r"(r[1]), "=r"(r[2]), "=r"(r[3]) : "r"(addr));
}
// bf16 inputs, f32 acc (GEMMs)
__device__ __forceinline__ void mma16816(float* c, const uint32_t* a, const uint32_t* b) {
    asm volatile("mma.sync.aligned.m16n8k16.row.col.f32.bf16.bf16.f32 "
                 "{%0,%1,%2,%3}, {%4,%5,%6,%7}, {%8,%9}, {%0,%1,%2,%3};"
                 : "+f"(c[0]), "+f"(c[1]), "+f"(c[2]), "+f"(c[3])
                 : "r"(a[0]), "r"(a[1]), "r"(a[2]), "r"(a[3]), "r"(b[0]), "r"(b[1]));
}
// fp16 inputs, f32 acc (flash)
__device__ __forceinline__ void mma_hf(float* c, const uint32_t* a, const uint32_t* b) {
    asm volatile("mma.sync.aligned.m16n8k16.row.col.f32.f16.f16.f32 "
                 "{%0,%1,%2,%3}, {%4,%5,%6,%7}, {%8,%9}, {%0,%1,%2,%3};"
                 : "+f"(c[0]), "+f"(c[1]), "+f"(c[2]), "+f"(c[3])
                 : "r"(a[0]), "r"(a[1]), "r"(a[2]), "r"(a[3]), "r"(b[0]), "r"(b[1]));
}
__device__ __forceinline__ float ex2(float x) {
    float y;
    asm("ex2.approx.f32 %0, %1;" : "=f"(y) : "f"(x));
    return y;
}
__device__ __forceinline__ uint32_t packh2(float x, float y) {
    __half2 t = __floats2half2_rn(x, y);
    return *reinterpret_cast<uint32_t*>(&t);
}
__device__ __forceinline__ uint32_t pack2_split(float x, float y, uint32_t& lopack) {
    __nv_bfloat16 hx = __float2bfloat16(x);
    __nv_bfloat16 hy = __float2bfloat16(y);
    __nv_bfloat16 lx = __float2bfloat16(x - __bfloat162float(hx));
    __nv_bfloat16 ly = __float2bfloat16(y - __bfloat162float(hy));
    lopack = (uint32_t)__bfloat16_as_ushort(lx) | ((uint32_t)__bfloat16_as_ushort(ly) << 16);
    return (uint32_t)__bfloat16_as_ushort(hx) | ((uint32_t)__bfloat16_as_ushort(hy) << 16);
}

// ---------------------------------------------------------------------------
// fp32 -> bf16 hi/lo splits (GEMM inputs)
// ---------------------------------------------------------------------------
__global__ void split_bf16(const float* __restrict__ in,
                           __nv_bfloat16* __restrict__ hi,
                           __nv_bfloat16* __restrict__ lo, int n4)
{
    int i = blockIdx.x * blockDim.x + threadIdx.x;
    if (i >= n4) return;
    float4 v = reinterpret_cast<const float4*>(in)[i];
    uint2 h, l;
    h.x = pack2_split(v.x, v.y, l.x);
    h.y = pack2_split(v.z, v.w, l.y);
    reinterpret_cast<uint2*>(hi)[i] = h;
    reinterpret_cast<uint2*>(lo)[i] = l;
}

__global__ void split_bf16_w(const float* __restrict__ w0, const float* __restrict__ w1,
                             const float* __restrict__ w2, const float* __restrict__ w3,
                             __nv_bfloat16* __restrict__ h0, __nv_bfloat16* __restrict__ l0,
                             __nv_bfloat16* __restrict__ h1, __nv_bfloat16* __restrict__ l1,
                             __nv_bfloat16* __restrict__ h2, __nv_bfloat16* __restrict__ l2,
                             __nv_bfloat16* __restrict__ h3, __nv_bfloat16* __restrict__ l3,
                             int n4)
{
    int i = blockIdx.x * blockDim.x + threadIdx.x;
    if (i >= n4) return;
    const float* in; __nv_bfloat16 *hi, *lo;
    switch (blockIdx.y) {
        case 0: in = w0; hi = h0; lo = l0; break;
        case 1: in = w1; hi = h1; lo = l1; break;
        case 2: in = w2; hi = h2; lo = l2; break;
        default: in = w3; hi = h3; lo = l3; break;
    }
    float4 v = reinterpret_cast<const float4*>(in)[i];
    uint2 h, l;
    h.x = pack2_split(v.x, v.y, l.x);
    h.y = pack2_split(v.z, v.w, l.y);
    reinterpret_cast<uint2*>(hi)[i] = h;
    reinterpret_cast<uint2*>(lo)[i] = l;
}

// ---------------------------------------------------------------------------
// HMMA bf16-split GEMM core (proven R7 version): 3-stage cp.async pipeline.
// MODE 0: fp32 C. MODE 1: SINGLE fp16 scatter to [bh][nseq][hd].
// ---------------------------------------------------------------------------
#define TM 128
#define TN 128
#define KC 32
#define CHUNKS (DMODEL / KC)       // 32
#define TILE_B  8192
#define STAGE_B (4 * TILE_B)       // 32 KB
#define GSTAGES 3
#define GEMM_DSMEM (GSTAGES * STAGE_B)   // 96 KB

__device__ __forceinline__ uint32_t swz(uint32_t row, uint32_t chunk) {
    return row * 64u + ((chunk ^ ((row >> 1) & 3u)) << 4);
}

template <int MODE>
__device__ __forceinline__ void gemm_core(
        const __nv_bfloat16* __restrict__ Ahi, const __nv_bfloat16* __restrict__ Alo,
        const __nv_bfloat16* __restrict__ Bhi, const __nv_bfloat16* __restrict__ Blo,
        const float* __restrict__ bias, float* __restrict__ C,
        __half* __restrict__ Cq, float scale, char* dsm, int m0, int n0)
{
    const uint32_t sbase = s2u(dsm);
    const int tid  = threadIdx.x;
    const int wid  = tid >> 5;
    const int lane = tid & 31;
    const int wm = (wid & 3) * 32;
    const int wn = (wid >> 2) * 64;

    float acc[2][8][4];
#pragma unroll
    for (int i = 0; i < 2; i++)
#pragma unroll
        for (int j = 0; j < 8; j++)
#pragma unroll
            for (int q = 0; q < 4; q++) acc[i][j][q] = 0.f;

    const uint32_t lrow = (uint32_t)(tid >> 1);
    const uint32_t lch  = (uint32_t)(tid & 1) * 2;

    auto load_chunk = [&](int ch, int s) {
        const uint32_t sb = sbase + (uint32_t)s * STAGE_B;
        const size_t gA = (size_t)(m0 + lrow) * DMODEL + (size_t)ch * KC + lch * 8;
        const size_t gB = (size_t)(n0 + lrow) * DMODEL + (size_t)ch * KC + lch * 8;
#pragma unroll
        for (int c = 0; c < 2; c++) {
            uint32_t so = swz(lrow, lch + c);
            cpa16(sb + 0 * TILE_B + so, Ahi + gA + c * 8);
            cpa16(sb + 1 * TILE_B + so, Alo + gA + c * 8);
            cpa16(sb + 2 * TILE_B + so, Bhi + gB + c * 8);
            cpa16(sb + 3 * TILE_B + so, Blo + gB + c * 8);
        }
        asm volatile("cp.async.commit_group;" ::: "memory");
    };

    load_chunk(0, 0);
    load_chunk(1, 1);

    int stage = 0;
    for (int ch = 0; ch < CHUNKS; ++ch) {
        if (ch + 1 < CHUNKS) { asm volatile("cp.async.wait_group 1;" ::: "memory"); }
        else                 { asm volatile("cp.async.wait_group 0;" ::: "memory"); }
        __syncthreads();
        if (ch + 2 < CHUNKS) {
            int ps = stage + 2; if (ps >= GSTAGES) ps -= GSTAGES;
            load_chunk(ch + 2, ps);
        }

        const uint32_t sb = sbase + (uint32_t)stage * STAGE_B;
#pragma unroll
        for (int kstep = 0; kstep < 2; kstep++) {
            const uint32_t kc = (uint32_t)kstep * 2;
            uint32_t a_hi[2][4], a_lo[2][4];
#pragma unroll
            for (int mf = 0; mf < 2; mf++) {
                uint32_t row = (uint32_t)(wm + mf * 16 + (lane & 15));
                uint32_t chn = kc + (uint32_t)(lane >> 4);
                ldsm_x4(a_hi[mf], sb + 0 * TILE_B + swz(row, chn));
                ldsm_x4(a_lo[mf], sb + 1 * TILE_B + swz(row, chn));
            }
#pragma unroll
            for (int nf2 = 0; nf2 < 4; nf2++) {
                uint32_t row = (uint32_t)(wn + nf2 * 16 + 8 * (lane >> 4) + (lane & 7));
                uint32_t chn = kc + (uint32_t)((lane >> 3) & 1);
                uint32_t th[4], tl[4];
                ldsm_x4(th, sb + 2 * TILE_B + swz(row, chn));
                ldsm_x4(tl, sb + 3 * TILE_B + swz(row, chn));
#pragma unroll
                for (int mf = 0; mf < 2; mf++) {
                    mma16816(acc[mf][2 * nf2],     a_hi[mf], th);
                    mma16816(acc[mf][2 * nf2 + 1], a_hi[mf], th + 2);
                    mma16816(acc[mf][2 * nf2],     a_hi[mf], tl);
                    mma16816(acc[mf][2 * nf2 + 1], a_hi[mf], tl + 2);
                    mma16816(acc[mf][2 * nf2],     a_lo[mf], th);
                    mma16816(acc[mf][2 * nf2 + 1], a_lo[mf], th + 2);
                }
            }
        }
        if (++stage >= GSTAGES) stage = 0;
    }
    __syncthreads();

#pragma unroll
    for (int mf = 0; mf < 2; mf++) {
        const int rbase = m0 + wm + mf * 16 + (lane >> 2);
#pragma unroll
        for (int nf = 0; nf < 8; nf++) {
            const int n = n0 + wn + nf * 8 + (lane & 3) * 2;
            const float b0 = bias[n], b1 = bias[n + 1];
#pragma unroll
            for (int half = 0; half < 2; half++) {
                const int m = rbase + half * 8;
                float v0 = (acc[mf][nf][2 * half] + b0) * scale;
                float v1 = (acc[mf][nf][2 * half + 1] + b1) * scale;
                if (MODE == 0) {
                    *reinterpret_cast<float2*>(C + (size_t)m * DMODEL + n) =
                        make_float2(v0, v1);
                } else {
                    int h = n >> 6, hd = n & 63;
                    int b  = m >> 11, ns = m & 2047;
                    size_t idx = (((size_t)(b * NHEAD + h) * NSEQ) + ns) * HDIM + hd;
                    *reinterpret_cast<uint32_t*>(Cq + idx) = packh2(v0, v1);
                }
            }
        }
    }
}

// Q pre-scale folds 1/sqrt(HDIM) AND log2(e)
#define QSCALE 0.18033688011112042f

__global__ void __launch_bounds__(256, 2)
gemm_qkv(const __nv_bfloat16* __restrict__ xhi, const __nv_bfloat16* __restrict__ xlo,
         const __nv_bfloat16* __restrict__ w0h, const __nv_bfloat16* __restrict__ w0l,
         const __nv_bfloat16* __restrict__ w1h, const __nv_bfloat16* __restrict__ w1l,
         const __nv_bfloat16* __restrict__ w2h, const __nv_bfloat16* __restrict__ w2l,
         const float* __restrict__ bq, const float* __restrict__ bk,
         const float* __restrict__ bv,
         __half* __restrict__ q, __half* __restrict__ k, __half* __restrict__ v)
{
    extern __shared__ char dsm[];
    const int m0 = blockIdx.y * TM;
    const int n0 = blockIdx.x * TN;
    const __nv_bfloat16 *Bh, *Bl; const float* bias;
    __half* Cq; float scale;
    switch (blockIdx.z) {
        case 0:  Bh = w0h; Bl = w0l; bias = bq; Cq = q; scale = QSCALE; break;
        case 1:  Bh = w1h; Bl = w1l; bias = bk; Cq = k; scale = 1.0f;   break;
        default: Bh = w2h; Bl = w2l; bias = bv; Cq = v; scale = 1.0f;   break;
    }
    gemm_core<1>(xhi, xlo, Bh, Bl, bias, nullptr, Cq, scale, dsm, m0, n0);
}

__global__ void __launch_bounds__(256, 2)
gemm_out(const __nv_bfloat16* __restrict__ Ahi, const __nv_bfloat16* __restrict__ Alo,
         const __nv_bfloat16* __restrict__ Bhi, const __nv_bfloat16* __restrict__ Blo,
         const float* __restrict__ bias, float* __restrict__ C)
{
    extern __shared__ char dsm[];
    gemm_core<0>(Ahi, Alo, Bhi, Blo, bias, C, nullptr, 1.0f, dsm,
                 blockIdx.y * TM, blockIdx.x * TN);
}

// ---------------------------------------------------------------------------
// Single-fp16 HMMA flash attention: 1 MMA per tile-pair for S and PV
// (3x fewer MMAs than split). fp32 accum + fp32 softmax stats.
// Q 16KB + 2 stages x (K 8KB + V 8KB) = 48 KB smem, occ 2.
// ---------------------------------------------------------------------------
#define FBR 128
#define FBC 64
#define FKT (NSEQ / FBC)          // 32
#define FQ 0
#define FSTG0 16384
#define FSTG_B 16384
#define FLASH_DSMEM (16384 + 2 * FSTG_B)   // 48 KB

__device__ __forceinline__ uint32_t swz8(uint32_t row, uint32_t chunk) {
    return row * 128u + ((chunk ^ (row & 7u)) << 4);
}

__global__ void __launch_bounds__(256, 2)
flash_mma(const __half* __restrict__ Q, const __half* __restrict__ K,
          const __half* __restrict__ V,
          __nv_bfloat16* __restrict__ Ohi, __nv_bfloat16* __restrict__ Olo)
{
    extern __shared__ char fsm[];
    const uint32_t sbase = s2u(fsm);

    const int tid  = threadIdx.x;
    const int wid  = tid >> 5;
    const int lane = tid & 31;
    const int bh   = blockIdx.y;
    const int q0   = blockIdx.x * FBR;

    const size_t hb = (size_t)bh * NSEQ * HDIM;
    const __half* Qb = Q + hb;
    const __half* Kb = K + hb;
    const __half* Vb = V + hb;

    // Q tile load (joins first KV commit group): 128 rows x 128B
    {
        const uint32_t row = (uint32_t)(tid >> 1);
        const uint32_t c0  = (uint32_t)(tid & 1) * 4;
        const size_t g = (size_t)(q0 + row) * HDIM + c0 * 8;
#pragma unroll
        for (int c = 0; c < 4; c++)
            cpa16(sbase + FQ + swz8(row, c0 + c), Qb + g + c * 8);
    }
    auto load_kv = [&](int kt, int s) {
        const uint32_t sb = sbase + FSTG0 + (uint32_t)s * FSTG_B;
        const uint32_t row = (uint32_t)(tid >> 2);
        const uint32_t cc  = (uint32_t)(tid & 3) * 2;
        const size_t g = (size_t)(kt * FBC + row) * HDIM + cc * 8;
#pragma unroll
        for (int j = 0; j < 2; j++) {
            uint32_t sw = swz8(row, cc + j);
            cpa16(sb +        sw, Kb + g + j * 8);
            cpa16(sb + 8192u + sw, Vb + g + j * 8);
        }
        asm volatile("cp.async.commit_group;" ::: "memory");
    };
    load_kv(0, 0);

    float o[8][4];
#pragma unroll
    for (int j = 0; j < 8; j++)
#pragma unroll
        for (int q = 0; q < 4; q++) o[j][q] = 0.f;
    float m0s = -1e30f, m1s = -1e30f, l0s = 0.f, l1s = 0.f;

    const uint32_t la15 = (uint32_t)(lane & 15);
    const uint32_t la7  = (uint32_t)(lane & 7);
    const uint32_t lb8  = 8u * (uint32_t)(lane >> 4);
    const uint32_t lbc  = (uint32_t)((lane >> 3) & 1);
    const uint32_t lac  = (uint32_t)(lane >> 4);

    for (int kt = 0; kt < FKT; kt++) {
        asm volatile("cp.async.wait_group 0;" ::: "memory");
        __syncthreads();
        if (kt + 1 < FKT) load_kv(kt + 1, (kt + 1) & 1);

        const uint32_t sb = sbase + FSTG0 + (uint32_t)(kt & 1) * FSTG_B;
        float acc[8][4];
#pragma unroll
        for (int j = 0; j < 8; j++)
#pragma unroll
            for (int q = 0; q < 4; q++) acc[j][q] = 0.f;

        // ---- S = Q K^T : 32 MMAs
#pragma unroll
        for (int kf = 0; kf < 4; kf++) {
            uint32_t aQ[4];
            ldsm_x4(aQ, sbase + FQ + swz8((uint32_t)(wid * 16) + la15, 2u * kf + lac));
#pragma unroll
            for (int np = 0; np < 4; np++) {
                uint32_t kh[4];
                ldsm_x4(kh, sb + swz8((uint32_t)(np * 16) + la7 + lb8, 2u * kf + lbc));
                mma_hf(acc[2 * np],     aQ, kh);
                mma_hf(acc[2 * np + 1], aQ, kh + 2);
            }
        }

        // ---- online softmax (base-2; single-MUFU ex2; fp32 stats)
        float mx0 = -1e30f, mx1 = -1e30f;
#pragma unroll
        for (int nf = 0; nf < 8; nf++) {
            mx0 = fmaxf(mx0, fmaxf(acc[nf][0], acc[nf][1]));
            mx1 = fmaxf(mx1, fmaxf(acc[nf][2], acc[nf][3]));
        }
        mx0 = fmaxf(mx0, __shfl_xor_sync(0xffffffffu, mx0, 1));
        mx0 = fmaxf(mx0, __shfl_xor_sync(0xffffffffu, mx0, 2));
        mx1 = fmaxf(mx1, __shfl_xor_sync(0xffffffffu, mx1, 1));
        mx1 = fmaxf(mx1, __shfl_xor_sync(0xffffffffu, mx1, 2));
        float mn0 = fmaxf(m0s, mx0), mn1 = fmaxf(m1s, mx1);
        float al0 = ex2(m0s - mn0), al1 = ex2(m1s - mn1);
        m0s = mn0; m1s = mn1;
        float sum0 = 0.f, sum1 = 0.f;
#pragma unroll
        for (int nf = 0; nf < 8; nf++) {
            acc[nf][0] = ex2(acc[nf][0] - mn0);
            acc[nf][1] = ex2(acc[nf][1] - mn0);
            acc[nf][2] = ex2(acc[nf][2] - mn1);
            acc[nf][3] = ex2(acc[nf][3] - mn1);
            sum0 += acc[nf][0] + acc[nf][1];
            sum1 += acc[nf][2] + acc[nf][3];
        }
        sum0 += __shfl_xor_sync(0xffffffffu, sum0, 1);
        sum0 += __shfl_xor_sync(0xffffffffu, sum0, 2);
        sum1 += __shfl_xor_sync(0xffffffffu, sum1, 1);
        sum1 += __shfl_xor_sync(0xffffffffu, sum1, 2);
        l0s = l0s * al0 + sum0;
        l1s = l1s * al1 + sum1;
#pragma unroll
        for (int nf = 0; nf < 8; nf++) {
            o[nf][0] *= al0; o[nf][1] *= al0;
            o[nf][2] *= al1; o[nf][3] *= al1;
        }

        // ---- O += P V : single-fp16 P, 32 MMAs
#pragma unroll
        for (int kf = 0; kf < 4; kf++) {
            uint32_t pP[4];
            pP[0] = packh2(acc[2 * kf][0],     acc[2 * kf][1]);
            pP[1] = packh2(acc[2 * kf][2],     acc[2 * kf][3]);
            pP[2] = packh2(acc[2 * kf + 1][0], acc[2 * kf + 1][1]);
            pP[3] = packh2(acc[2 * kf + 1][2], acc[2 * kf + 1][3]);
#pragma unroll
            for (int dp = 0; dp < 4; dp++) {
                uint32_t vh[4];
                ldsm_x4_t(vh, sb + 8192u +
                              swz8((uint32_t)(kf * 16) + la15, 2u * dp + lac));
                mma_hf(o[2 * dp],     pP, vh);
                mma_hf(o[2 * dp + 1], pP, vh + 2);
            }
        }
    }

    // ---- normalize + write bf16 hi/lo to [B,N,D] (O-proj needs split precision)
    const int bb = bh >> 4;
    const int h  = bh & 15;
    const float inv0 = 1.f / l0s, inv1 = 1.f / l1s;
    const int qlo = q0 + wid * 16 + (lane >> 2);
#pragma unroll
    for (int nf = 0; nf < 8; nf++) {
        const int gcol = h * HDIM + nf * 8 + (lane & 3) * 2;
        uint32_t lp, hp;
        hp = pack2_split(o[nf][0] * inv0, o[nf][1] * inv0, lp);
        size_t i0 = ((size_t)(bb * NSEQ + qlo)) * DMODEL + gcol;
        *reinterpret_cast<uint32_t*>(Ohi + i0) = hp;
        *reinterpret_cast<uint32_t*>(Olo + i0) = lp;
        hp = pack2_split(o[nf][2] * inv1, o[nf][3] * inv1, lp);
        size_t i1 = ((size_t)(bb * NSEQ + qlo + 8)) * DMODEL + gcol;
        *reinterpret_cast<uint32_t*>(Ohi + i1) = hp;
        *reinterpret_cast<uint32_t*>(Olo + i1) = lp;
    }
}

// ---------------------------------------------------------------------------
// Launch
// ---------------------------------------------------------------------------
extern "C" void kernel_launch(void* const* d_in, const int* in_sizes, int n_in,
                              void* d_out, int out_size)
{
    const float* x  = (const float*)d_in[0];
    const float* Wq = (const float*)d_in[1];
    const float* bq = (const float*)d_in[2];
    const float* Wk = (const float*)d_in[3];
    const float* bk = (const float*)d_in[4];
    const float* Wv = (const float*)d_in[5];
    const float* bv = (const float*)d_in[6];
    const float* Wo = (const float*)d_in[7];
    const float* bo = (const float*)d_in[8];
    float* out = (float*)d_out;

    __nv_bfloat16 *xhi, *xlo, *w0h, *w0l, *w1h, *w1l, *w2h, *w2l, *w3h, *w3l, *ahi, *alo;
    __half *qp, *kp, *vp;
    cudaGetSymbolAddress((void**)&xhi, g_xhi);  cudaGetSymbolAddress((void**)&xlo, g_xlo);
    cudaGetSymbolAddress((void**)&w0h, g_W0hi); cudaGetSymbolAddress((void**)&w0l, g_W0lo);
    cudaGetSymbolAddress((void**)&w1h, g_W1hi); cudaGetSymbolAddress((void**)&w1l, g_W1lo);
    cudaGetSymbolAddress((void**)&w2h, g_W2hi); cudaGetSymbolAddress((void**)&w2l, g_W2lo);
    cudaGetSymbolAddress((void**)&w3h, g_W3hi); cudaGetSymbolAddress((void**)&w3l, g_W3lo);
    cudaGetSymbolAddress((void**)&ahi, g_Ahi);  cudaGetSymbolAddress((void**)&alo, g_Alo);
    cudaGetSymbolAddress((void**)&qp, g_Q);
    cudaGetSymbolAddress((void**)&kp, g_K);
    cudaGetSymbolAddress((void**)&vp, g_V);

    cudaFuncSetAttribute(gemm_qkv, cudaFuncAttributeMaxDynamicSharedMemorySize, GEMM_DSMEM);
    cudaFuncSetAttribute(gemm_out, cudaFuncAttributeMaxDynamicSharedMemorySize, GEMM_DSMEM);
    cudaFuncSetAttribute(flash_mma, cudaFuncAttributeMaxDynamicSharedMemorySize, FLASH_DSMEM);

    split_bf16<<<MTOT * DMODEL / 4 / 256, 256>>>(x, xhi, xlo, MTOT * DMODEL / 4);
    dim3 wgrid(DMODEL * DMODEL / 4 / 256, 4);
    split_bf16_w<<<wgrid, 256>>>(Wq, Wk, Wv, Wo,
                                 w0h, w0l, w1h, w1l, w2h, w2l, w3h, w3l,
                                 DMODEL * DMODEL / 4);

    dim3 qgrid(DMODEL / TN, MTOT / TM, 3);   // (8, 32, 3)
    gemm_qkv<<<qgrid, 256, GEMM_DSMEM>>>(xhi, xlo, w0h, w0l, w1h, w1l, w2h, w2l,
                                         bq, bk, bv, qp, kp, vp);

    dim3 agrid(NSEQ / FBR, BH);              // (16, 32)
    flash_mma<<<agrid, 256, FLASH_DSMEM>>>(qp, kp, vp, ahi, alo);

    dim3 ogrid(DMODEL / TN, MTOT / TM);      // (8, 32)
    gemm_out<<<ogrid, 256, GEMM_DSMEM>>>(ahi, alo, w3h, w3l, bo, out);
}

// round 14
// speedup vs baseline: 2.3756x; 1.6778x over previous
#include <cuda_runtime.h>
#include <cuda_bf16.h>
#include <cuda_fp16.h>
#include <cstddef>
#include <cstdint>

// Problem constants
#define B_SZ   2
#define NSEQ   2048
#define DMODEL 1024
#define NHEAD  16
#define HDIM   64
#define MTOT   (B_SZ * NSEQ)      // 4096
#define BH     (B_SZ * NHEAD)     // 32

// ---------------------------------------------------------------------------
// Scratch (static device arrays; no allocation allowed) — all single fp16
// ---------------------------------------------------------------------------
__device__ __half g_x[MTOT * DMODEL];
__device__ __half g_W0[DMODEL * DMODEL];
__device__ __half g_W1[DMODEL * DMODEL];
__device__ __half g_W2[DMODEL * DMODEL];
__device__ __half g_W3[DMODEL * DMODEL];
__device__ __half g_A[MTOT * DMODEL];
__device__ __half g_Q[BH * NSEQ * HDIM];
__device__ __half g_K[BH * NSEQ * HDIM];
__device__ __half g_V[BH * NSEQ * HDIM];

// ---------------------------------------------------------------------------
// PTX helpers
// ---------------------------------------------------------------------------
__device__ __forceinline__ uint32_t s2u(const void* p) {
    uint32_t r;
    asm("{ .reg .u64 t; cvta.to.shared.u64 t, %1; cvt.u32.u64 %0, t; }" : "=r"(r) : "l"(p));
    return r;
}
__device__ __forceinline__ void cpa16(uint32_t dst, const void* src) {
    asm volatile("cp.async.cg.shared.global [%0], [%1], 16;" :: "r"(dst), "l"(src));
}
__device__ __forceinline__ void ldsm_x4(uint32_t* r, uint32_t addr) {
    asm volatile("ldmatrix.sync.aligned.m8n8.x4.shared.b16 {%0,%1,%2,%3}, [%4];"
                 : "=r"(r[0]), "=r"(r[1]), "=r"(r[2]), "=r"(r[3]) : "r"(addr));
}
__device__ __forceinline__ void ldsm_x4_t(uint32_t* r, uint32_t addr) {
    asm volatile("ldmatrix.sync.aligned.m8n8.x4.trans.shared.b16 {%0,%1,%2,%3}, [%4];"
                 : "=r"(r[0]), "=r"(r[1]), "=r"(r[2]), "=r"(r[3]) : "r"(addr));
}
// fp16 inputs, f32 acc
__device__ __forceinline__ void mma_hf(float* c, const uint32_t* a, const uint32_t* b) {
    asm volatile("mma.sync.aligned.m16n8k16.row.col.f32.f16.f16.f32 "
                 "{%0,%1,%2,%3}, {%4,%5,%6,%7}, {%8,%9}, {%0,%1,%2,%3};"
                 : "+f"(c[0]), "+f"(c[1]), "+f"(c[2]), "+f"(c[3])
                 : "r"(a[0]), "r"(a[1]), "r"(a[2]), "r"(a[3]), "r"(b[0]), "r"(b[1]));
}
__device__ __forceinline__ float ex2(float x) {
    float y;
    asm("ex2.approx.f32 %0, %1;" : "=f"(y) : "f"(x));
    return y;
}
__device__ __forceinline__ uint32_t packh2(float x, float y) {
    __half2 t = __floats2half2_rn(x, y);
    return *reinterpret_cast<uint32_t*>(&t);
}

// ---------------------------------------------------------------------------
// fp32 -> fp16 converts
// ---------------------------------------------------------------------------
__global__ void conv_f16(const float* __restrict__ in, __half* __restrict__ o, int n4)
{
    int i = blockIdx.x * blockDim.x + threadIdx.x;
    if (i >= n4) return;
    float4 v = reinterpret_cast<const float4*>(in)[i];
    uint2 h;
    h.x = packh2(v.x, v.y);
    h.y = packh2(v.z, v.w);
    reinterpret_cast<uint2*>(o)[i] = h;
}

__global__ void conv_f16_w(const float* __restrict__ w0, const float* __restrict__ w1,
                           const float* __restrict__ w2, const float* __restrict__ w3,
                           __half* __restrict__ o0, __half* __restrict__ o1,
                           __half* __restrict__ o2, __half* __restrict__ o3, int n4)
{
    int i = blockIdx.x * blockDim.x + threadIdx.x;
    if (i >= n4) return;
    const float* in; __half* o;
    switch (blockIdx.y) {
        case 0: in = w0; o = o0; break;
        case 1: in = w1; o = o1; break;
        case 2: in = w2; o = o2; break;
        default: in = w3; o = o3; break;
    }
    float4 v = reinterpret_cast<const float4*>(in)[i];
    uint2 h;
    h.x = packh2(v.x, v.y);
    h.y = packh2(v.z, v.w);
    reinterpret_cast<uint2*>(o)[i] = h;
}

// ---------------------------------------------------------------------------
// Single-fp16 HMMA GEMM: 1 MMA per tile (3x fewer than split).
// CTA 128x128, K-chunk 32, 3-stage cp.async.
// MODE 0: fp32 C row-major. MODE 1: fp16 scatter to [bh][nseq][hd].
// ---------------------------------------------------------------------------
#define TM 128
#define TN 128
#define KC 32
#define CHUNKS (DMODEL / KC)       // 32
#define TILE_B  8192               // 128 rows x 64 B
#define STAGE_B (2 * TILE_B)       // 16 KB (A + B)
#define GSTAGES 3
#define GEMM_DSMEM (GSTAGES * STAGE_B)   // 48 KB

__device__ __forceinline__ uint32_t swz(uint32_t row, uint32_t chunk) {
    return row * 64u + ((chunk ^ ((row >> 1) & 3u)) << 4);
}

template <int MODE>
__device__ __forceinline__ void gemm_core(
        const __half* __restrict__ A, const __half* __restrict__ B,
        const float* __restrict__ bias, float* __restrict__ C,
        __half* __restrict__ Cq, float scale, char* dsm, int m0, int n0)
{
    const uint32_t sbase = s2u(dsm);
    const int tid  = threadIdx.x;
    const int wid  = tid >> 5;
    const int lane = tid & 31;
    const int wm = (wid & 3) * 32;
    const int wn = (wid >> 2) * 64;

    float acc[2][8][4];
#pragma unroll
    for (int i = 0; i < 2; i++)
#pragma unroll
        for (int j = 0; j < 8; j++)
#pragma unroll
            for (int q = 0; q < 4; q++) acc[i][j][q] = 0.f;

    const uint32_t lrow = (uint32_t)(tid >> 1);
    const uint32_t lch  = (uint32_t)(tid & 1) * 2;

    auto load_chunk = [&](int ch, int s) {
        const uint32_t sb = sbase + (uint32_t)s * STAGE_B;
        const size_t gA = (size_t)(m0 + lrow) * DMODEL + (size_t)ch * KC + lch * 8;
        const size_t gB = (size_t)(n0 + lrow) * DMODEL + (size_t)ch * KC + lch * 8;
#pragma unroll
        for (int c = 0; c < 2; c++) {
            uint32_t so = swz(lrow, lch + c);
            cpa16(sb +          so, A + gA + c * 8);
            cpa16(sb + TILE_B + so, B + gB + c * 8);
        }
        asm volatile("cp.async.commit_group;" ::: "memory");
    };

    load_chunk(0, 0);
    load_chunk(1, 1);

    int stage = 0;
    for (int ch = 0; ch < CHUNKS; ++ch) {
        if (ch + 1 < CHUNKS) { asm volatile("cp.async.wait_group 1;" ::: "memory"); }
        else                 { asm volatile("cp.async.wait_group 0;" ::: "memory"); }
        __syncthreads();
        if (ch + 2 < CHUNKS) {
            int ps = stage + 2; if (ps >= GSTAGES) ps -= GSTAGES;
            load_chunk(ch + 2, ps);
        }

        const uint32_t sb = sbase + (uint32_t)stage * STAGE_B;
#pragma unroll
        for (int kstep = 0; kstep < 2; kstep++) {
            const uint32_t kc = (uint32_t)kstep * 2;
            uint32_t a_f[2][4];
#pragma unroll
            for (int mf = 0; mf < 2; mf++) {
                uint32_t row = (uint32_t)(wm + mf * 16 + (lane & 15));
                uint32_t chn = kc + (uint32_t)(lane >> 4);
                ldsm_x4(a_f[mf], sb + swz(row, chn));
            }
#pragma unroll
            for (int nf2 = 0; nf2 < 4; nf2++) {
                uint32_t row = (uint32_t)(wn + nf2 * 16 + 8 * (lane >> 4) + (lane & 7));
                uint32_t chn = kc + (uint32_t)((lane >> 3) & 1);
                uint32_t th[4];
                ldsm_x4(th, sb + TILE_B + swz(row, chn));
#pragma unroll
                for (int mf = 0; mf < 2; mf++) {
                    mma_hf(acc[mf][2 * nf2],     a_f[mf], th);
                    mma_hf(acc[mf][2 * nf2 + 1], a_f[mf], th + 2);
                }
            }
        }
        if (++stage >= GSTAGES) stage = 0;
    }
    __syncthreads();

#pragma unroll
    for (int mf = 0; mf < 2; mf++) {
        const int rbase = m0 + wm + mf * 16 + (lane >> 2);
#pragma unroll
        for (int nf = 0; nf < 8; nf++) {
            const int n = n0 + wn + nf * 8 + (lane & 3) * 2;
            const float b0 = bias[n], b1 = bias[n + 1];
#pragma unroll
            for (int half = 0; half < 2; half++) {
                const int m = rbase + half * 8;
                float v0 = (acc[mf][nf][2 * half] + b0) * scale;
                float v1 = (acc[mf][nf][2 * half + 1] + b1) * scale;
                if (MODE == 0) {
                    *reinterpret_cast<float2*>(C + (size_t)m * DMODEL + n) =
                        make_float2(v0, v1);
                } else {
                    int h = n >> 6, hd = n & 63;
                    int b  = m >> 11, ns = m & 2047;
                    size_t idx = (((size_t)(b * NHEAD + h) * NSEQ) + ns) * HDIM + hd;
                    *reinterpret_cast<uint32_t*>(Cq + idx) = packh2(v0, v1);
                }
            }
        }
    }
}

// Q pre-scale folds 1/sqrt(HDIM) AND log2(e)
#define QSCALE 0.18033688011112042f

__global__ void __launch_bounds__(256, 2)
gemm_qkv(const __half* __restrict__ x,
         const __half* __restrict__ w0, const __half* __restrict__ w1,
         const __half* __restrict__ w2,
         const float* __restrict__ bq, const float* __restrict__ bk,
         const float* __restrict__ bv,
         __half* __restrict__ q, __half* __restrict__ k, __half* __restrict__ v)
{
    extern __shared__ char dsm[];
    const int m0 = blockIdx.y * TM;
    const int n0 = blockIdx.x * TN;
    const __half* W; const float* bias;
    __half* Cq; float scale;
    switch (blockIdx.z) {
        case 0:  W = w0; bias = bq; Cq = q; scale = QSCALE; break;
        case 1:  W = w1; bias = bk; Cq = k; scale = 1.0f;   break;
        default: W = w2; bias = bv; Cq = v; scale = 1.0f;   break;
    }
    gemm_core<1>(x, W, bias, nullptr, Cq, scale, dsm, m0, n0);
}

__global__ void __launch_bounds__(256, 2)
gemm_out(const __half* __restrict__ A, const __half* __restrict__ W,
         const float* __restrict__ bias, float* __restrict__ C)
{
    extern __shared__ char dsm[];
    gemm_core<0>(A, W, bias, C, nullptr, 1.0f, dsm,
                 blockIdx.y * TM, blockIdx.x * TN);
}

// ---------------------------------------------------------------------------
// Single-fp16 HMMA flash attention (proven R13 kernel; epilogue -> fp16 A).
// ---------------------------------------------------------------------------
#define FBR 128
#define FBC 64
#define FKT (NSEQ / FBC)          // 32
#define FQ 0
#define FSTG0 16384
#define FSTG_B 16384
#define FLASH_DSMEM (16384 + 2 * FSTG_B)   // 48 KB

__device__ __forceinline__ uint32_t swz8(uint32_t row, uint32_t chunk) {
    return row * 128u + ((chunk ^ (row & 7u)) << 4);
}

__global__ void __launch_bounds__(256, 2)
flash_mma(const __half* __restrict__ Q, const __half* __restrict__ K,
          const __half* __restrict__ V, __half* __restrict__ Ao)
{
    extern __shared__ char fsm[];
    const uint32_t sbase = s2u(fsm);

    const int tid  = threadIdx.x;
    const int wid  = tid >> 5;
    const int lane = tid & 31;
    const int bh   = blockIdx.y;
    const int q0   = blockIdx.x * FBR;

    const size_t hb = (size_t)bh * NSEQ * HDIM;
    const __half* Qb = Q + hb;
    const __half* Kb = K + hb;
    const __half* Vb = V + hb;

    {
        const uint32_t row = (uint32_t)(tid >> 1);
        const uint32_t c0  = (uint32_t)(tid & 1) * 4;
        const size_t g = (size_t)(q0 + row) * HDIM + c0 * 8;
#pragma unroll
        for (int c = 0; c < 4; c++)
            cpa16(sbase + FQ + swz8(row, c0 + c), Qb + g + c * 8);
    }
    auto load_kv = [&](int kt, int s) {
        const uint32_t sb = sbase + FSTG0 + (uint32_t)s * FSTG_B;
        const uint32_t row = (uint32_t)(tid >> 2);
        const uint32_t cc  = (uint32_t)(tid & 3) * 2;
        const size_t g = (size_t)(kt * FBC + row) * HDIM + cc * 8;
#pragma unroll
        for (int j = 0; j < 2; j++) {
            uint32_t sw = swz8(row, cc + j);
            cpa16(sb +        sw, Kb + g + j * 8);
            cpa16(sb + 8192u + sw, Vb + g + j * 8);
        }
        asm volatile("cp.async.commit_group;" ::: "memory");
    };
    load_kv(0, 0);

    float o[8][4];
#pragma unroll
    for (int j = 0; j < 8; j++)
#pragma unroll
        for (int q = 0; q < 4; q++) o[j][q] = 0.f;
    float m0s = -1e30f, m1s = -1e30f, l0s = 0.f, l1s = 0.f;

    const uint32_t la15 = (uint32_t)(lane & 15);
    const uint32_t la7  = (uint32_t)(lane & 7);
    const uint32_t lb8  = 8u * (uint32_t)(lane >> 4);
    const uint32_t lbc  = (uint32_t)((lane >> 3) & 1);
    const uint32_t lac  = (uint32_t)(lane >> 4);

    for (int kt = 0; kt < FKT; kt++) {
        asm volatile("cp.async.wait_group 0;" ::: "memory");
        __syncthreads();
        if (kt + 1 < FKT) load_kv(kt + 1, (kt + 1) & 1);

        const uint32_t sb = sbase + FSTG0 + (uint32_t)(kt & 1) * FSTG_B;
        float acc[8][4];
#pragma unroll
        for (int j = 0; j < 8; j++)
#pragma unroll
            for (int q = 0; q < 4; q++) acc[j][q] = 0.f;

        // ---- S = Q K^T : 32 MMAs
#pragma unroll
        for (int kf = 0; kf < 4; kf++) {
            uint32_t aQ[4];
            ldsm_x4(aQ, sbase + FQ + swz8((uint32_t)(wid * 16) + la15, 2u * kf + lac));
#pragma unroll
            for (int np = 0; np < 4; np++) {
                uint32_t kh[4];
                ldsm_x4(kh, sb + swz8((uint32_t)(np * 16) + la7 + lb8, 2u * kf + lbc));
                mma_hf(acc[2 * np],     aQ, kh);
                mma_hf(acc[2 * np + 1], aQ, kh + 2);
            }
        }

        // ---- online softmax (base-2; single-MUFU ex2; fp32 stats)
        float mx0 = -1e30f, mx1 = -1e30f;
#pragma unroll
        for (int nf = 0; nf < 8; nf++) {
            mx0 = fmaxf(mx0, fmaxf(acc[nf][0], acc[nf][1]));
            mx1 = fmaxf(mx1, fmaxf(acc[nf][2], acc[nf][3]));
        }
        mx0 = fmaxf(mx0, __shfl_xor_sync(0xffffffffu, mx0, 1));
        mx0 = fmaxf(mx0, __shfl_xor_sync(0xffffffffu, mx0, 2));
        mx1 = fmaxf(mx1, __shfl_xor_sync(0xffffffffu, mx1, 1));
        mx1 = fmaxf(mx1, __shfl_xor_sync(0xffffffffu, mx1, 2));
        float mn0 = fmaxf(m0s, mx0), mn1 = fmaxf(m1s, mx1);
        float al0 = ex2(m0s - mn0), al1 = ex2(m1s - mn1);
        m0s = mn0; m1s = mn1;
        float sum0 = 0.f, sum1 = 0.f;
#pragma unroll
        for (int nf = 0; nf < 8; nf++) {
            acc[nf][0] = ex2(acc[nf][0] - mn0);
            acc[nf][1] = ex2(acc[nf][1] - mn0);
            acc[nf][2] = ex2(acc[nf][2] - mn1);
            acc[nf][3] = ex2(acc[nf][3] - mn1);
            sum0 += acc[nf][0] + acc[nf][1];
            sum1 += acc[nf][2] + acc[nf][3];
        }
        sum0 += __shfl_xor_sync(0xffffffffu, sum0, 1);
        sum0 += __shfl_xor_sync(0xffffffffu, sum0, 2);
        sum1 += __shfl_xor_sync(0xffffffffu, sum1, 1);
        sum1 += __shfl_xor_sync(0xffffffffu, sum1, 2);
        l0s = l0s * al0 + sum0;
        l1s = l1s * al1 + sum1;
#pragma unroll
        for (int nf = 0; nf < 8; nf++) {
            o[nf][0] *= al0; o[nf][1] *= al0;
            o[nf][2] *= al1; o[nf][3] *= al1;
        }

        // ---- O += P V : single-fp16 P, 32 MMAs
#pragma unroll
        for (int kf = 0; kf < 4; kf++) {
            uint32_t pP[4];
            pP[0] = packh2(acc[2 * kf][0],     acc[2 * kf][1]);
            pP[1] = packh2(acc[2 * kf][2],     acc[2 * kf][3]);
            pP[2] = packh2(acc[2 * kf + 1][0], acc[2 * kf + 1][1]);
            pP[3] = packh2(acc[2 * kf + 1][2], acc[2 * kf + 1][3]);
#pragma unroll
            for (int dp = 0; dp < 4; dp++) {
                uint32_t vh[4];
                ldsm_x4_t(vh, sb + 8192u +
                              swz8((uint32_t)(kf * 16) + la15, 2u * dp + lac));
                mma_hf(o[2 * dp],     pP, vh);
                mma_hf(o[2 * dp + 1], pP, vh + 2);
            }
        }
    }

    // ---- normalize + write single fp16 A in [B,N,D]
    const int bb = bh >> 4;
    const int h  = bh & 15;
    const float inv0 = 1.f / l0s, inv1 = 1.f / l1s;
    const int qlo = q0 + wid * 16 + (lane >> 2);
#pragma unroll
    for (int nf = 0; nf < 8; nf++) {
        const int gcol = h * HDIM + nf * 8 + (lane & 3) * 2;
        size_t i0 = ((size_t)(bb * NSEQ + qlo)) * DMODEL + gcol;
        *reinterpret_cast<uint32_t*>(Ao + i0) = packh2(o[nf][0] * inv0, o[nf][1] * inv0);
        size_t i1 = ((size_t)(bb * NSEQ + qlo + 8)) * DMODEL + gcol;
        *reinterpret_cast<uint32_t*>(Ao + i1) = packh2(o[nf][2] * inv1, o[nf][3] * inv1);
    }
}

// ---------------------------------------------------------------------------
// Launch
// ---------------------------------------------------------------------------
extern "C" void kernel_launch(void* const* d_in, const int* in_sizes, int n_in,
                              void* d_out, int out_size)
{
    const float* x  = (const float*)d_in[0];
    const float* Wq = (const float*)d_in[1];
    const float* bq = (const float*)d_in[2];
    const float* Wk = (const float*)d_in[3];
    const float* bk = (const float*)d_in[4];
    const float* Wv = (const float*)d_in[5];
    const float* bv = (const float*)d_in[6];
    const float* Wo = (const float*)d_in[7];
    const float* bo = (const float*)d_in[8];
    float* out = (float*)d_out;

    __half *xp, *w0, *w1, *w2, *w3, *ap, *qp, *kp, *vp;
    cudaGetSymbolAddress((void**)&xp, g_x);
    cudaGetSymbolAddress((void**)&w0, g_W0);
    cudaGetSymbolAddress((void**)&w1, g_W1);
    cudaGetSymbolAddress((void**)&w2, g_W2);
    cudaGetSymbolAddress((void**)&w3, g_W3);
    cudaGetSymbolAddress((void**)&ap, g_A);
    cudaGetSymbolAddress((void**)&qp, g_Q);
    cudaGetSymbolAddress((void**)&kp, g_K);
    cudaGetSymbolAddress((void**)&vp, g_V);

    cudaFuncSetAttribute(gemm_qkv, cudaFuncAttributeMaxDynamicSharedMemorySize, GEMM_DSMEM);
    cudaFuncSetAttribute(gemm_out, cudaFuncAttributeMaxDynamicSharedMemorySize, GEMM_DSMEM);
    cudaFuncSetAttribute(flash_mma, cudaFuncAttributeMaxDynamicSharedMemorySize, FLASH_DSMEM);

    conv_f16<<<MTOT * DMODEL / 4 / 256, 256>>>(x, xp, MTOT * DMODEL / 4);
    dim3 wgrid(DMODEL * DMODEL / 4 / 256, 4);
    conv_f16_w<<<wgrid, 256>>>(Wq, Wk, Wv, Wo, w0, w1, w2, w3, DMODEL * DMODEL / 4);

    dim3 qgrid(DMODEL / TN, MTOT / TM, 3);   // (8, 32, 3)
    gemm_qkv<<<qgrid, 256, GEMM_DSMEM>>>(xp, w0, w1, w2, bq, bk, bv, qp, kp, vp);

    dim3 agrid(NSEQ / FBR, BH);              // (16, 32)
    flash_mma<<<agrid, 256, FLASH_DSMEM>>>(qp, kp, vp, ap);

    dim3 ogrid(DMODEL / TN, MTOT / TM);      // (8, 32)
    gemm_out<<<ogrid, 256, GEMM_DSMEM>>>(ap, w3, bo, out);
}

// round 15
// speedup vs baseline: 2.4401x; 1.0272x over previous
#include <cuda_runtime.h>
#include <cuda_bf16.h>
#include <cuda_fp16.h>
#include <cstddef>
#include <cstdint>

// Problem constants
#define B_SZ   2
#define NSEQ   2048
#define DMODEL 1024
#define NHEAD  16
#define HDIM   64
#define MTOT   (B_SZ * NSEQ)      // 4096
#define BH     (B_SZ * NHEAD)     // 32

// ---------------------------------------------------------------------------
// Scratch (static device arrays; no allocation allowed) — all single fp16
// ---------------------------------------------------------------------------
__device__ __half g_x[MTOT * DMODEL];
__device__ __half g_W0[DMODEL * DMODEL];
__device__ __half g_W1[DMODEL * DMODEL];
__device__ __half g_W2[DMODEL * DMODEL];
__device__ __half g_W3[DMODEL * DMODEL];
__device__ __half g_A[MTOT * DMODEL];
__device__ __half g_Q[BH * NSEQ * HDIM];
__device__ __half g_K[BH * NSEQ * HDIM];
__device__ __half g_V[BH * NSEQ * HDIM];

// ---------------------------------------------------------------------------
// PTX helpers
// ---------------------------------------------------------------------------
__device__ __forceinline__ uint32_t s2u(const void* p) {
    uint32_t r;
    asm("{ .reg .u64 t; cvta.to.shared.u64 t, %1; cvt.u32.u64 %0, t; }" : "=r"(r) : "l"(p));
    return r;
}
__device__ __forceinline__ void cpa16(uint32_t dst, const void* src) {
    asm volatile("cp.async.cg.shared.global [%0], [%1], 16;" :: "r"(dst), "l"(src));
}
__device__ __forceinline__ void ldsm_x4(uint32_t* r, uint32_t addr) {
    asm volatile("ldmatrix.sync.aligned.m8n8.x4.shared.b16 {%0,%1,%2,%3}, [%4];"
                 : "=r"(r[0]), "=r"(r[1]), "=r"(r[2]), "=r"(r[3]) : "r"(addr));
}
__device__ __forceinline__ void ldsm_x4_t(uint32_t* r, uint32_t addr) {
    asm volatile("ldmatrix.sync.aligned.m8n8.x4.trans.shared.b16 {%0,%1,%2,%3}, [%4];"
                 : "=r"(r[0]), "=r"(r[1]), "=r"(r[2]), "=r"(r[3]) : "r"(addr));
}
// fp16 inputs, f32 acc
__device__ __forceinline__ void mma_hf(float* c, const uint32_t* a, const uint32_t* b) {
    asm volatile("mma.sync.aligned.m16n8k16.row.col.f32.f16.f16.f32 "
                 "{%0,%1,%2,%3}, {%4,%5,%6,%7}, {%8,%9}, {%0,%1,%2,%3};"
                 : "+f"(c[0]), "+f"(c[1]), "+f"(c[2]), "+f"(c[3])
                 : "r"(a[0]), "r"(a[1]), "r"(a[2]), "r"(a[3]), "r"(b[0]), "r"(b[1]));
}
__device__ __forceinline__ float ex2(float x) {
    float y;
    asm("ex2.approx.f32 %0, %1;" : "=f"(y) : "f"(x));
    return y;
}
// packed fp16x2 exp2 — one MUFU op yields two P values already in fp16
__device__ __forceinline__ uint32_t ex2_h2(uint32_t x) {
    uint32_t y;
    asm("ex2.approx.f16x2 %0, %1;" : "=r"(y) : "r"(x));
    return y;
}
__device__ __forceinline__ uint32_t packh2(float x, float y) {
    __half2 t = __floats2half2_rn(x, y);
    return *reinterpret_cast<uint32_t*>(&t);
}
__device__ __forceinline__ float2 unpackh2(uint32_t p) {
    return __half22float2(*reinterpret_cast<__half2*>(&p));
}

// ---------------------------------------------------------------------------
// fp32 -> fp16 converts
// ---------------------------------------------------------------------------
__global__ void conv_f16(const float* __restrict__ in, __half* __restrict__ o, int n4)
{
    int i = blockIdx.x * blockDim.x + threadIdx.x;
    if (i >= n4) return;
    float4 v = reinterpret_cast<const float4*>(in)[i];
    uint2 h;
    h.x = packh2(v.x, v.y);
    h.y = packh2(v.z, v.w);
    reinterpret_cast<uint2*>(o)[i] = h;
}

__global__ void conv_f16_w(const float* __restrict__ w0, const float* __restrict__ w1,
                           const float* __restrict__ w2, const float* __restrict__ w3,
                           __half* __restrict__ o0, __half* __restrict__ o1,
                           __half* __restrict__ o2, __half* __restrict__ o3, int n4)
{
    int i = blockIdx.x * blockDim.x + threadIdx.x;
    if (i >= n4) return;
    const float* in; __half* o;
    switch (blockIdx.y) {
        case 0: in = w0; o = o0; break;
        case 1: in = w1; o = o1; break;
        case 2: in = w2; o = o2; break;
        default: in = w3; o = o3; break;
    }
    float4 v = reinterpret_cast<const float4*>(in)[i];
    uint2 h;
    h.x = packh2(v.x, v.y);
    h.y = packh2(v.z, v.w);
    reinterpret_cast<uint2*>(o)[i] = h;
}

// ---------------------------------------------------------------------------
// Single-fp16 HMMA GEMM (proven R14): CTA 128x128, K-chunk 32, 3-stage cp.async.
// MODE 0: fp32 C row-major. MODE 1: fp16 scatter to [bh][nseq][hd].
// ---------------------------------------------------------------------------
#define TM 128
#define TN 128
#define KC 32
#define CHUNKS (DMODEL / KC)       // 32
#define TILE_B  8192               // 128 rows x 64 B
#define STAGE_B (2 * TILE_B)       // 16 KB (A + B)
#define GSTAGES 3
#define GEMM_DSMEM (GSTAGES * STAGE_B)   // 48 KB

__device__ __forceinline__ uint32_t swz(uint32_t row, uint32_t chunk) {
    return row * 64u + ((chunk ^ ((row >> 1) & 3u)) << 4);
}

template <int MODE>
__device__ __forceinline__ void gemm_core(
        const __half* __restrict__ A, const __half* __restrict__ B,
        const float* __restrict__ bias, float* __restrict__ C,
        __half* __restrict__ Cq, float scale, char* dsm, int m0, int n0)
{
    const uint32_t sbase = s2u(dsm);
    const int tid  = threadIdx.x;
    const int wid  = tid >> 5;
    const int lane = tid & 31;
    const int wm = (wid & 3) * 32;
    const int wn = (wid >> 2) * 64;

    float acc[2][8][4];
#pragma unroll
    for (int i = 0; i < 2; i++)
#pragma unroll
        for (int j = 0; j < 8; j++)
#pragma unroll
            for (int q = 0; q < 4; q++) acc[i][j][q] = 0.f;

    const uint32_t lrow = (uint32_t)(tid >> 1);
    const uint32_t lch  = (uint32_t)(tid & 1) * 2;

    auto load_chunk = [&](int ch, int s) {
        const uint32_t sb = sbase + (uint32_t)s * STAGE_B;
        const size_t gA = (size_t)(m0 + lrow) * DMODEL + (size_t)ch * KC + lch * 8;
        const size_t gB = (size_t)(n0 + lrow) * DMODEL + (size_t)ch * KC + lch * 8;
#pragma unroll
        for (int c = 0; c < 2; c++) {
            uint32_t so = swz(lrow, lch + c);
            cpa16(sb +          so, A + gA + c * 8);
            cpa16(sb + TILE_B + so, B + gB + c * 8);
        }
        asm volatile("cp.async.commit_group;" ::: "memory");
    };

    load_chunk(0, 0);
    load_chunk(1, 1);

    int stage = 0;
    for (int ch = 0; ch < CHUNKS; ++ch) {
        if (ch + 1 < CHUNKS) { asm volatile("cp.async.wait_group 1;" ::: "memory"); }
        else                 { asm volatile("cp.async.wait_group 0;" ::: "memory"); }
        __syncthreads();
        if (ch + 2 < CHUNKS) {
            int ps = stage + 2; if (ps >= GSTAGES) ps -= GSTAGES;
            load_chunk(ch + 2, ps);
        }

        const uint32_t sb = sbase + (uint32_t)stage * STAGE_B;
#pragma unroll
        for (int kstep = 0; kstep < 2; kstep++) {
            const uint32_t kc = (uint32_t)kstep * 2;
            uint32_t a_f[2][4];
#pragma unroll
            for (int mf = 0; mf < 2; mf++) {
                uint32_t row = (uint32_t)(wm + mf * 16 + (lane & 15));
                uint32_t chn = kc + (uint32_t)(lane >> 4);
                ldsm_x4(a_f[mf], sb + swz(row, chn));
            }
#pragma unroll
            for (int nf2 = 0; nf2 < 4; nf2++) {
                uint32_t row = (uint32_t)(wn + nf2 * 16 + 8 * (lane >> 4) + (lane & 7));
                uint32_t chn = kc + (uint32_t)((lane >> 3) & 1);
                uint32_t th[4];
                ldsm_x4(th, sb + TILE_B + swz(row, chn));
#pragma unroll
                for (int mf = 0; mf < 2; mf++) {
                    mma_hf(acc[mf][2 * nf2],     a_f[mf], th);
                    mma_hf(acc[mf][2 * nf2 + 1], a_f[mf], th + 2);
                }
            }
        }
        if (++stage >= GSTAGES) stage = 0;
    }
    __syncthreads();

#pragma unroll
    for (int mf = 0; mf < 2; mf++) {
        const int rbase = m0 + wm + mf * 16 + (lane >> 2);
#pragma unroll
        for (int nf = 0; nf < 8; nf++) {
            const int n = n0 + wn + nf * 8 + (lane & 3) * 2;
            const float b0 = bias[n], b1 = bias[n + 1];
#pragma unroll
            for (int half = 0; half < 2; half++) {
                const int m = rbase + half * 8;
                float v0 = (acc[mf][nf][2 * half] + b0) * scale;
                float v1 = (acc[mf][nf][2 * half + 1] + b1) * scale;
                if (MODE == 0) {
                    *reinterpret_cast<float2*>(C + (size_t)m * DMODEL + n) =
                        make_float2(v0, v1);
                } else {
                    int h = n >> 6, hd = n & 63;
                    int b  = m >> 11, ns = m & 2047;
                    size_t idx = (((size_t)(b * NHEAD + h) * NSEQ) + ns) * HDIM + hd;
                    *reinterpret_cast<uint32_t*>(Cq + idx) = packh2(v0, v1);
                }
            }
        }
    }
}

// Q pre-scale folds 1/sqrt(HDIM) AND log2(e)
#define QSCALE 0.18033688011112042f

__global__ void __launch_bounds__(256, 2)
gemm_qkv(const __half* __restrict__ x,
         const __half* __restrict__ w0, const __half* __restrict__ w1,
         const __half* __restrict__ w2,
         const float* __restrict__ bq, const float* __restrict__ bk,
         const float* __restrict__ bv,
         __half* __restrict__ q, __half* __restrict__ k, __half* __restrict__ v)
{
    extern __shared__ char dsm[];
    const int m0 = blockIdx.y * TM;
    const int n0 = blockIdx.x * TN;
    const __half* W; const float* bias;
    __half* Cq; float scale;
    switch (blockIdx.z) {
        case 0:  W = w0; bias = bq; Cq = q; scale = QSCALE; break;
        case 1:  W = w1; bias = bk; Cq = k; scale = 1.0f;   break;
        default: W = w2; bias = bv; Cq = v; scale = 1.0f;   break;
    }
    gemm_core<1>(x, W, bias, nullptr, Cq, scale, dsm, m0, n0);
}

__global__ void __launch_bounds__(256, 2)
gemm_out(const __half* __restrict__ A, const __half* __restrict__ W,
         const float* __restrict__ bias, float* __restrict__ C)
{
    extern __shared__ char dsm[];
    gemm_core<0>(A, W, bias, C, nullptr, 1.0f, dsm,
                 blockIdx.y * TM, blockIdx.x * TN);
}

// ---------------------------------------------------------------------------
// Single-fp16 HMMA flash attention with fp16x2 exponent:
// ex2.approx.f16x2 emits P fragments directly (MUFU ops halved, packs removed).
// ---------------------------------------------------------------------------
#define FBR 128
#define FBC 64
#define FKT (NSEQ / FBC)          // 32
#define FQ 0
#define FSTG0 16384
#define FSTG_B 16384
#define FLASH_DSMEM (16384 + 2 * FSTG_B)   // 48 KB

__device__ __forceinline__ uint32_t swz8(uint32_t row, uint32_t chunk) {
    return row * 128u + ((chunk ^ (row & 7u)) << 4);
}

__global__ void __launch_bounds__(256, 2)
flash_mma(const __half* __restrict__ Q, const __half* __restrict__ K,
          const __half* __restrict__ V, __half* __restrict__ Ao)
{
    extern __shared__ char fsm[];
    const uint32_t sbase = s2u(fsm);

    const int tid  = threadIdx.x;
    const int wid  = tid >> 5;
    const int lane = tid & 31;
    const int bh   = blockIdx.y;
    const int q0   = blockIdx.x * FBR;

    const size_t hb = (size_t)bh * NSEQ * HDIM;
    const __half* Qb = Q + hb;
    const __half* Kb = K + hb;
    const __half* Vb = V + hb;

    {
        const uint32_t row = (uint32_t)(tid >> 1);
        const uint32_t c0  = (uint32_t)(tid & 1) * 4;
        const size_t g = (size_t)(q0 + row) * HDIM + c0 * 8;
#pragma unroll
        for (int c = 0; c < 4; c++)
            cpa16(sbase + FQ + swz8(row, c0 + c), Qb + g + c * 8);
    }
    auto load_kv = [&](int kt, int s) {
        const uint32_t sb = sbase + FSTG0 + (uint32_t)s * FSTG_B;
        const uint32_t row = (uint32_t)(tid >> 2);
        const uint32_t cc  = (uint32_t)(tid & 3) * 2;
        const size_t g = (size_t)(kt * FBC + row) * HDIM + cc * 8;
#pragma unroll
        for (int j = 0; j < 2; j++) {
            uint32_t sw = swz8(row, cc + j);
            cpa16(sb +        sw, Kb + g + j * 8);
            cpa16(sb + 8192u + sw, Vb + g + j * 8);
        }
        asm volatile("cp.async.commit_group;" ::: "memory");
    };
    load_kv(0, 0);

    float o[8][4];
#pragma unroll
    for (int j = 0; j < 8; j++)
#pragma unroll
        for (int q = 0; q < 4; q++) o[j][q] = 0.f;
    float m0s = -1e30f, m1s = -1e30f, l0s = 0.f, l1s = 0.f;

    const uint32_t la15 = (uint32_t)(lane & 15);
    const uint32_t la7  = (uint32_t)(lane & 7);
    const uint32_t lb8  = 8u * (uint32_t)(lane >> 4);
    const uint32_t lbc  = (uint32_t)((lane >> 3) & 1);
    const uint32_t lac  = (uint32_t)(lane >> 4);

    for (int kt = 0; kt < FKT; kt++) {
        asm volatile("cp.async.wait_group 0;" ::: "memory");
        __syncthreads();
        if (kt + 1 < FKT) load_kv(kt + 1, (kt + 1) & 1);

        const uint32_t sb = sbase + FSTG0 + (uint32_t)(kt & 1) * FSTG_B;
        float acc[8][4];
#pragma unroll
        for (int j = 0; j < 8; j++)
#pragma unroll
            for (int q = 0; q < 4; q++) acc[j][q] = 0.f;

        // ---- S = Q K^T : 32 MMAs
#pragma unroll
        for (int kf = 0; kf < 4; kf++) {
            uint32_t aQ[4];
            ldsm_x4(aQ, sbase + FQ + swz8((uint32_t)(wid * 16) + la15, 2u * kf + lac));
#pragma unroll
            for (int np = 0; np < 4; np++) {
                uint32_t kh[4];
                ldsm_x4(kh, sb + swz8((uint32_t)(np * 16) + la7 + lb8, 2u * kf + lbc));
                mma_hf(acc[2 * np],     aQ, kh);
                mma_hf(acc[2 * np + 1], aQ, kh + 2);
            }
        }

        // ---- online softmax: max (fp32) -> packed fp16x2 exp -> fp32 sums
        float mx0 = -1e30f, mx1 = -1e30f;
#pragma unroll
        for (int nf = 0; nf < 8; nf++) {
            mx0 = fmaxf(mx0, fmaxf(acc[nf][0], acc[nf][1]));
            mx1 = fmaxf(mx1, fmaxf(acc[nf][2], acc[nf][3]));
        }
        mx0 = fmaxf(mx0, __shfl_xor_sync(0xffffffffu, mx0, 1));
        mx0 = fmaxf(mx0, __shfl_xor_sync(0xffffffffu, mx0, 2));
        mx1 = fmaxf(mx1, __shfl_xor_sync(0xffffffffu, mx1, 1));
        mx1 = fmaxf(mx1, __shfl_xor_sync(0xffffffffu, mx1, 2));
        float mn0 = fmaxf(m0s, mx0), mn1 = fmaxf(m1s, mx1);
        float al0 = ex2(m0s - mn0), al1 = ex2(m1s - mn1);
        m0s = mn0; m1s = mn1;

        // P fragments directly from ex2.f16x2 (A-frag layout: rows pair, cols pair)
        uint32_t pP[4][4];
        float sum0 = 0.f, sum1 = 0.f;
#pragma unroll
        for (int kf = 0; kf < 4; kf++) {
            pP[kf][0] = ex2_h2(packh2(acc[2 * kf][0] - mn0,     acc[2 * kf][1] - mn0));
            pP[kf][1] = ex2_h2(packh2(acc[2 * kf][2] - mn1,     acc[2 * kf][3] - mn1));
            pP[kf][2] = ex2_h2(packh2(acc[2 * kf + 1][0] - mn0, acc[2 * kf + 1][1] - mn0));
            pP[kf][3] = ex2_h2(packh2(acc[2 * kf + 1][2] - mn1, acc[2 * kf + 1][3] - mn1));
            float2 f0 = unpackh2(pP[kf][0]);
            float2 f1 = unpackh2(pP[kf][1]);
            float2 f2 = unpackh2(pP[kf][2]);
            float2 f3 = unpackh2(pP[kf][3]);
            sum0 += (f0.x + f0.y) + (f2.x + f2.y);
            sum1 += (f1.x + f1.y) + (f3.x + f3.y);
        }
        sum0 += __shfl_xor_sync(0xffffffffu, sum0, 1);
        sum0 += __shfl_xor_sync(0xffffffffu, sum0, 2);
        sum1 += __shfl_xor_sync(0xffffffffu, sum1, 1);
        sum1 += __shfl_xor_sync(0xffffffffu, sum1, 2);
        l0s = l0s * al0 + sum0;
        l1s = l1s * al1 + sum1;
#pragma unroll
        for (int nf = 0; nf < 8; nf++) {
            o[nf][0] *= al0; o[nf][1] *= al0;
            o[nf][2] *= al1; o[nf][3] *= al1;
        }

        // ---- O += P V : 32 MMAs, pP already packed
#pragma unroll
        for (int kf = 0; kf < 4; kf++) {
#pragma unroll
            for (int dp = 0; dp < 4; dp++) {
                uint32_t vh[4];
                ldsm_x4_t(vh, sb + 8192u +
                              swz8((uint32_t)(kf * 16) + la15, 2u * dp + lac));
                mma_hf(o[2 * dp],     pP[kf], vh);
                mma_hf(o[2 * dp + 1], pP[kf], vh + 2);
            }
        }
    }

    // ---- normalize + write single fp16 A in [B,N,D]
    const int bb = bh >> 4;
    const int h  = bh & 15;
    const float inv0 = 1.f / l0s, inv1 = 1.f / l1s;
    const int qlo = q0 + wid * 16 + (lane >> 2);
#pragma unroll
    for (int nf = 0; nf < 8; nf++) {
        const int gcol = h * HDIM + nf * 8 + (lane & 3) * 2;
        size_t i0 = ((size_t)(bb * NSEQ + qlo)) * DMODEL + gcol;
        *reinterpret_cast<uint32_t*>(Ao + i0) = packh2(o[nf][0] * inv0, o[nf][1] * inv0);
        size_t i1 = ((size_t)(bb * NSEQ + qlo + 8)) * DMODEL + gcol;
        *reinterpret_cast<uint32_t*>(Ao + i1) = packh2(o[nf][2] * inv1, o[nf][3] * inv1);
    }
}

// ---------------------------------------------------------------------------
// Launch
// ---------------------------------------------------------------------------
extern "C" void kernel_launch(void* const* d_in, const int* in_sizes, int n_in,
                              void* d_out, int out_size)
{
    const float* x  = (const float*)d_in[0];
    const float* Wq = (const float*)d_in[1];
    const float* bq = (const float*)d_in[2];
    const float* Wk = (const float*)d_in[3];
    const float* bk = (const float*)d_in[4];
    const float* Wv = (const float*)d_in[5];
    const float* bv = (const float*)d_in[6];
    const float* Wo = (const float*)d_in[7];
    const float* bo = (const float*)d_in[8];
    float* out = (float*)d_out;

    __half *xp, *w0, *w1, *w2, *w3, *ap, *qp, *kp, *vp;
    cudaGetSymbolAddress((void**)&xp, g_x);
    cudaGetSymbolAddress((void**)&w0, g_W0);
    cudaGetSymbolAddress((void**)&w1, g_W1);
    cudaGetSymbolAddress((void**)&w2, g_W2);
    cudaGetSymbolAddress((void**)&w3, g_W3);
    cudaGetSymbolAddress((void**)&ap, g_A);
    cudaGetSymbolAddress((void**)&qp, g_Q);
    cudaGetSymbolAddress((void**)&kp, g_K);
    cudaGetSymbolAddress((void**)&vp, g_V);

    cudaFuncSetAttribute(gemm_qkv, cudaFuncAttributeMaxDynamicSharedMemorySize, GEMM_DSMEM);
    cudaFuncSetAttribute(gemm_out, cudaFuncAttributeMaxDynamicSharedMemorySize, GEMM_DSMEM);
    cudaFuncSetAttribute(flash_mma, cudaFuncAttributeMaxDynamicSharedMemorySize, FLASH_DSMEM);

    conv_f16<<<MTOT * DMODEL / 4 / 256, 256>>>(x, xp, MTOT * DMODEL / 4);
    dim3 wgrid(DMODEL * DMODEL / 4 / 256, 4);
    conv_f16_w<<<wgrid, 256>>>(Wq, Wk, Wv, Wo, w0, w1, w2, w3, DMODEL * DMODEL / 4);

    dim3 qgrid(DMODEL / TN, MTOT / TM, 3);   // (8, 32, 3)
    gemm_qkv<<<qgrid, 256, GEMM_DSMEM>>>(xp, w0, w1, w2, bq, bk, bv, qp, kp, vp);

    dim3 agrid(NSEQ / FBR, BH);              // (16, 32)
    flash_mma<<<agrid, 256, FLASH_DSMEM>>>(qp, kp, vp, ap);

    dim3 ogrid(DMODEL / TN, MTOT / TM);      // (8, 32)
    gemm_out<<<ogrid, 256, GEMM_DSMEM>>>(ap, w3, bo, out);
}